// round 1
// baseline (speedup 1.0000x reference)
#include <cuda_runtime.h>
#include <cuda_bf16.h>
#include <cstdint>

#define B_  32
#define N_  4096
#define CI_ 128
#define CO_ 128
#define M_  256

// Scratch (no allocations allowed)
__device__ float g_xspec[B_ * M_ * CI_];   // [b][m][c]   4 MB
__device__ float g_ospec[B_ * M_ * CO_];   // [b][m][o]   4 MB
__device__ float g_Ut[M_ * N_];            // [m][n]      4 MB
__device__ float g_Wt[M_ * CI_ * CO_];     // [m][c][o]  16 MB

// ---------- packed f32x2 helpers ----------
__device__ __forceinline__ unsigned long long pk2(float lo, float hi) {
    unsigned long long r;
    asm("mov.b64 %0, {%1, %2};" : "=l"(r) : "f"(lo), "f"(hi));
    return r;
}
__device__ __forceinline__ unsigned long long ffma2(unsigned long long a,
                                                    unsigned long long b,
                                                    unsigned long long c) {
    unsigned long long d;
    asm("fma.rn.f32x2 %0, %1, %2, %3;" : "=l"(d) : "l"(a), "l"(b), "l"(c));
    return d;
}
__device__ __forceinline__ void upk2(unsigned long long v, float& lo, float& hi) {
    asm("mov.b64 {%0, %1}, %2;" : "=f"(lo), "=f"(hi) : "l"(v));
}

// ---------- transpose U: [N, M] -> Ut[M, N] ----------
__global__ void kTransU(const float* __restrict__ U) {
    __shared__ float tile[32][33];
    int m0 = blockIdx.x * 32, n0 = blockIdx.y * 32;
    int tx = threadIdx.x, ty = threadIdx.y;  // 32 x 8
#pragma unroll
    for (int j = 0; j < 4; j++)
        tile[ty + j * 8][tx] = U[(size_t)(n0 + ty + j * 8) * M_ + m0 + tx];
    __syncthreads();
#pragma unroll
    for (int j = 0; j < 4; j++)
        g_Ut[(size_t)(m0 + ty + j * 8) * N_ + n0 + tx] = tile[tx][ty + j * 8];
}

// ---------- transpose W: [c][o][m] -> Wt[m][c][o] ----------
__global__ void kTransW(const float* __restrict__ W) {
    __shared__ float tile[32][33];
    int m0 = blockIdx.x * 32, o0 = blockIdx.y * 32, c = blockIdx.z;
    int tx = threadIdx.x, ty = threadIdx.y;  // 32 x 8
    const float* Wc = W + (size_t)c * CO_ * M_;
#pragma unroll
    for (int j = 0; j < 4; j++)  // tile[o_loc][m_loc]
        tile[ty + j * 8][tx] = Wc[(size_t)(o0 + ty + j * 8) * M_ + m0 + tx];
    __syncthreads();
#pragma unroll
    for (int j = 0; j < 4; j++)
        g_Wt[(size_t)(m0 + ty + j * 8) * CI_ * CO_ + (size_t)c * CO_ + o0 + tx] =
            tile[tx][ty + j * 8];
}

// ---------- generic batched TN GEMM ----------
// C[b][p][q] = sum_k A[b][k][p] * B[b][k][q]
// A, B stored K-major (row = k). Tiles: 64(p) x 64(q) x 16(k), 256 threads,
// 4x4 micro-tile via packed FFMA2.
__global__ void __launch_bounds__(256) kGemmTN(
    const float* __restrict__ A, long lda, long sA,
    const float* __restrict__ Bm, long ldb, long sB,
    float* __restrict__ Cm, long ldc, long sC, int K)
{
    __shared__ float As[16][64];
    __shared__ float Bs[16][64];

    int bz = blockIdx.z;
    const float* Ab = A + (size_t)bz * sA;
    const float* Bb = Bm + (size_t)bz * sB;
    float* Cb = Cm + (size_t)bz * sC;

    int p0 = blockIdx.y * 64, q0 = blockIdx.x * 64;
    int t = threadIdx.x;
    int lr = t >> 4;             // load row (k), 0..15
    int lc = (t & 15) << 2;      // load col, float4
    int ty = t >> 4;             // p micro-tile
    int tx = t & 15;             // q micro-tile

    unsigned long long acc[4][2];
#pragma unroll
    for (int i = 0; i < 4; i++) { acc[i][0] = 0ull; acc[i][1] = 0ull; }

    for (int k0 = 0; k0 < K; k0 += 16) {
        *(float4*)&As[lr][lc] = *(const float4*)&Ab[(size_t)(k0 + lr) * lda + p0 + lc];
        *(float4*)&Bs[lr][lc] = *(const float4*)&Bb[(size_t)(k0 + lr) * ldb + q0 + lc];
        __syncthreads();
#pragma unroll
        for (int k = 0; k < 16; k++) {
            float4 a4 = *(const float4*)&As[k][ty << 2];
            float4 b4 = *(const float4*)&Bs[k][tx << 2];
            unsigned long long b01 = pk2(b4.x, b4.y);
            unsigned long long b23 = pk2(b4.z, b4.w);
            float av[4] = {a4.x, a4.y, a4.z, a4.w};
#pragma unroll
            for (int i = 0; i < 4; i++) {
                unsigned long long ad = pk2(av[i], av[i]);
                acc[i][0] = ffma2(ad, b01, acc[i][0]);
                acc[i][1] = ffma2(ad, b23, acc[i][1]);
            }
        }
        __syncthreads();
    }

#pragma unroll
    for (int i = 0; i < 4; i++) {
        float4 v;
        upk2(acc[i][0], v.x, v.y);
        upk2(acc[i][1], v.z, v.w);
        *(float4*)&Cb[(size_t)(p0 + (ty << 2) + i) * ldc + q0 + (tx << 2)] = v;
    }
}

// ---------- per-mode channel mixing ----------
// g_ospec[b][m][o] = sum_c g_xspec[b][m][c] * Wt[m][c][o]
// one block per m; 256 threads compute 32(b) x 128(o) via 4x4 micro-tiles.
__global__ void __launch_bounds__(256) kMix() {
    __shared__ float xs[32][128];   // [b][c]
    __shared__ float ws[16][128];   // [c-chunk][o]
    int m = blockIdx.x;
    int t = threadIdx.x;

    // load xs: 4096 floats = 1024 float4, 4 per thread (coalesced per b-row)
#pragma unroll
    for (int i = 0; i < 4; i++) {
        int idx = i * 256 + t;
        int bb = idx >> 5;
        int cc = (idx & 31) << 2;
        *(float4*)&xs[bb][cc] =
            *(const float4*)&g_xspec[((size_t)bb * M_ + m) * CI_ + cc];
    }

    int tx = t & 31;   // o micro-tile (4 o)
    int ty = t >> 5;   // b micro-tile (4 b)
    unsigned long long acc[4][2];
#pragma unroll
    for (int i = 0; i < 4; i++) { acc[i][0] = 0ull; acc[i][1] = 0ull; }

    const float* Wm = g_Wt + (size_t)m * CI_ * CO_;
    for (int c0 = 0; c0 < CI_; c0 += 16) {
        __syncthreads();
#pragma unroll
        for (int i = 0; i < 2; i++) {
            int idx = i * 256 + t;
            int cr = idx >> 5;
            int oc = (idx & 31) << 2;
            *(float4*)&ws[cr][oc] = *(const float4*)&Wm[(size_t)(c0 + cr) * CO_ + oc];
        }
        __syncthreads();
#pragma unroll
        for (int k = 0; k < 16; k++) {
            float4 b4 = *(const float4*)&ws[k][tx << 2];
            unsigned long long b01 = pk2(b4.x, b4.y);
            unsigned long long b23 = pk2(b4.z, b4.w);
#pragma unroll
            for (int i = 0; i < 4; i++) {
                float a = xs[(ty << 2) + i][c0 + k];
                unsigned long long ad = pk2(a, a);
                acc[i][0] = ffma2(ad, b01, acc[i][0]);
                acc[i][1] = ffma2(ad, b23, acc[i][1]);
            }
        }
    }

#pragma unroll
    for (int i = 0; i < 4; i++) {
        float4 v;
        upk2(acc[i][0], v.x, v.y);
        upk2(acc[i][1], v.z, v.w);
        int bb = (ty << 2) + i;
        *(float4*)&g_ospec[((size_t)bb * M_ + m) * CO_ + (tx << 2)] = v;
    }
}

extern "C" void kernel_launch(void* const* d_in, const int* in_sizes, int n_in,
                              void* d_out, int out_size) {
    const float* x = (const float*)d_in[0];   // [B, N, C_in]
    const float* U = (const float*)d_in[1];   // [N, M]
    const float* W = (const float*)d_in[2];   // [C_in, C_out, M]
    // d_in[3] = W_imag, unused (output only depends on real part)
    float* out = (float*)d_out;               // [B, N, C_out]

    float *pXs, *pOs, *pUt;
    cudaGetSymbolAddress((void**)&pXs, g_xspec);
    cudaGetSymbolAddress((void**)&pOs, g_ospec);
    cudaGetSymbolAddress((void**)&pUt, g_Ut);

    // 1) transposes (U -> Ut for the inverse GFT; W -> Wt[m][c][o])
    kTransU<<<dim3(M_ / 32, N_ / 32), dim3(32, 8)>>>(U);
    kTransW<<<dim3(M_ / 32, CO_ / 32, CI_), dim3(32, 8)>>>(W);

    // 2) forward GFT: x_spec[b][m][c] = sum_n U[n][m] * x[b][n][c]
    //    P = M (256), Q = C_in (128), K = N (4096)
    kGemmTN<<<dim3(CI_ / 64, M_ / 64, B_), 256>>>(
        U, M_, 0,
        x, CI_, (long)N_ * CI_,
        pXs, CI_, (long)M_ * CI_, N_);

    // 3) per-mode mixing
    kMix<<<M_, 256>>>();

    // 4) inverse GFT: out[b][n][o] = sum_m Ut[m][n] * ospec[b][m][o]
    //    P = N (4096), Q = C_out (128), K = M (256)
    kGemmTN<<<dim3(CO_ / 64, N_ / 64, B_), 256>>>(
        pUt, N_, 0,
        pOs, CO_, (long)M_ * CO_,
        out, CO_, (long)N_ * CO_, M_);
}

// round 3
// speedup vs baseline: 2.2056x; 2.2056x over previous
#include <cuda_runtime.h>
#include <cuda_bf16.h>
#include <cstdint>

#define B_  32
#define N_  4096
#define CI_ 128
#define CO_ 128
#define M_  256
#define KSPLIT 4

// ---------------- device scratch (no allocations allowed) ----------------
__device__ float g_xspecP[(size_t)KSPLIT * B_ * M_ * CI_];  // partial x_spec  16 MB
__device__ float g_ospec[B_ * M_ * CO_];                    // [b][m][o]        4 MB
__device__ float g_Wt[M_ * CI_ * CO_];                      // [m][c][o]       16 MB
__device__ __nv_bfloat16 g_Uthi[M_ * N_];                   // Ut hi [m][n]
__device__ __nv_bfloat16 g_Utlo[M_ * N_];
__device__ __nv_bfloat16 g_Uhi[N_ * M_];                    // U hi [n][m]
__device__ __nv_bfloat16 g_Ulo[N_ * M_];
__device__ __nv_bfloat16 g_xThi[(size_t)B_ * CI_ * N_];     // xT hi [b][c][n]
__device__ __nv_bfloat16 g_xTlo[(size_t)B_ * CI_ * N_];
__device__ __nv_bfloat16 g_oThi[B_ * CO_ * M_];             // ospecT hi [b][o][m]
__device__ __nv_bfloat16 g_oTlo[B_ * CO_ * M_];

// ---------------- helpers ----------------
__device__ __forceinline__ void split2(float v, __nv_bfloat16& h, __nv_bfloat16& l) {
    h = __float2bfloat16(v);
    l = __float2bfloat16(v - __bfloat162float(h));
}
__device__ __forceinline__ uint32_t s2u(const void* p) {
    uint32_t a;
    asm("{ .reg .u64 t; cvta.to.shared.u64 t, %1; cvt.u32.u64 %0, t; }" : "=r"(a) : "l"(p));
    return a;
}
#define SW128(o) ((o) ^ (((o) >> 3) & 0x70))

#define LDSM4(d0, d1, d2, d3, addr)                                                  \
    asm volatile("ldmatrix.sync.aligned.m8n8.x4.shared.b16 {%0,%1,%2,%3}, [%4];"     \
                 : "=r"(d0), "=r"(d1), "=r"(d2), "=r"(d3) : "r"(addr))

#define MMA16816(d0, d1, d2, d3, a0, a1, a2, a3, b0, b1)                             \
    asm volatile("mma.sync.aligned.m16n8k16.row.col.f32.bf16.bf16.f32 "              \
                 "{%0,%1,%2,%3},{%4,%5,%6,%7},{%8,%9},{%0,%1,%2,%3};"                \
                 : "+f"(d0), "+f"(d1), "+f"(d2), "+f"(d3)                            \
                 : "r"(a0), "r"(a1), "r"(a2), "r"(a3), "r"(b0), "r"(b1))

// packed f32x2 (for kMix)
__device__ __forceinline__ unsigned long long pk2(float lo, float hi) {
    unsigned long long r;
    asm("mov.b64 %0, {%1, %2};" : "=l"(r) : "f"(lo), "f"(hi));
    return r;
}
__device__ __forceinline__ unsigned long long ffma2(unsigned long long a,
                                                    unsigned long long b,
                                                    unsigned long long c) {
    unsigned long long d;
    asm("fma.rn.f32x2 %0, %1, %2, %3;" : "=l"(d) : "l"(a), "l"(b), "l"(c));
    return d;
}
__device__ __forceinline__ void upk2(unsigned long long v, float& lo, float& hi) {
    asm("mov.b64 {%0, %1}, %2;" : "=f"(lo), "=f"(hi) : "l"(v));
}

// ---------------- prep kernels ----------------
__global__ void kSplitTransU(const float* __restrict__ U) {
    __shared__ float tile[32][33];
    int m0 = blockIdx.x * 32, n0 = blockIdx.y * 32;
    int tx = threadIdx.x, ty = threadIdx.y;  // 32 x 8
#pragma unroll
    for (int j = 0; j < 4; j++) {
        int nl = ty + j * 8;
        float v = U[(size_t)(n0 + nl) * M_ + m0 + tx];
        tile[nl][tx] = v;
        __nv_bfloat16 h, l; split2(v, h, l);
        g_Uhi[(size_t)(n0 + nl) * M_ + m0 + tx] = h;
        g_Ulo[(size_t)(n0 + nl) * M_ + m0 + tx] = l;
    }
    __syncthreads();
#pragma unroll
    for (int j = 0; j < 4; j++) {
        int ml = ty + j * 8;
        float v = tile[tx][ml];
        __nv_bfloat16 h, l; split2(v, h, l);
        g_Uthi[(size_t)(m0 + ml) * N_ + n0 + tx] = h;
        g_Utlo[(size_t)(m0 + ml) * N_ + n0 + tx] = l;
    }
}

__global__ void kSplitTransX(const float* __restrict__ x) {
    __shared__ float tile[32][33];
    int n0 = blockIdx.x * 32, c0 = blockIdx.y * 32, b = blockIdx.z;
    int tx = threadIdx.x, ty = threadIdx.y;
    const float* xb = x + (size_t)b * N_ * CI_;
#pragma unroll
    for (int j = 0; j < 4; j++)
        tile[ty + j * 8][tx] = xb[(size_t)(n0 + ty + j * 8) * CI_ + c0 + tx];
    __syncthreads();
    __nv_bfloat16* oh = g_xThi + (size_t)b * CI_ * N_;
    __nv_bfloat16* ol = g_xTlo + (size_t)b * CI_ * N_;
#pragma unroll
    for (int j = 0; j < 4; j++) {
        int cl = ty + j * 8;
        float v = tile[tx][cl];
        __nv_bfloat16 h, l; split2(v, h, l);
        oh[(size_t)(c0 + cl) * N_ + n0 + tx] = h;
        ol[(size_t)(c0 + cl) * N_ + n0 + tx] = l;
    }
}

__global__ void kTransW(const float* __restrict__ W) {
    __shared__ float tile[32][33];
    int m0 = blockIdx.x * 32, o0 = blockIdx.y * 32, c = blockIdx.z;
    int tx = threadIdx.x, ty = threadIdx.y;
    const float* Wc = W + (size_t)c * CO_ * M_;
#pragma unroll
    for (int j = 0; j < 4; j++)
        tile[ty + j * 8][tx] = Wc[(size_t)(o0 + ty + j * 8) * M_ + m0 + tx];
    __syncthreads();
#pragma unroll
    for (int j = 0; j < 4; j++)
        g_Wt[(size_t)(m0 + ty + j * 8) * CI_ * CO_ + (size_t)c * CO_ + o0 + tx] =
            tile[tx][ty + j * 8];
}

// ospec[b][m][o] -> oT hi/lo [b][o][m]
__global__ void kSplitTransO() {
    __shared__ float tile[32][33];
    int m0 = blockIdx.x * 32, o0 = blockIdx.y * 32, b = blockIdx.z;
    int tx = threadIdx.x, ty = threadIdx.y;
    const float* ob = g_ospec + (size_t)b * M_ * CO_;
#pragma unroll
    for (int j = 0; j < 4; j++)  // tile[m_local][o_local], coalesced load over o
        tile[ty + j * 8][tx] = ob[(size_t)(m0 + ty + j * 8) * CO_ + o0 + tx];
    __syncthreads();
    __nv_bfloat16* oh = g_oThi + (size_t)b * CO_ * M_;
    __nv_bfloat16* ol = g_oTlo + (size_t)b * CO_ * M_;
#pragma unroll
    for (int j = 0; j < 4; j++) {
        int olc = ty + j * 8;
        float v = tile[tx][olc];  // = ospec[m0+tx][o0+olc]
        __nv_bfloat16 h, l; split2(v, h, l);
        oh[(size_t)(o0 + olc) * M_ + m0 + tx] = h;
        ol[(size_t)(o0 + olc) * M_ + m0 + tx] = l;
    }
}

// ---------------- split-bf16 TN GEMM via mma.sync (HMMA) ----------------
// D[row][col] = sum_k A[row][k] * B[col][k]; 128x128 CTA tile, 8 warps 2x4,
// warp tile 64x32, K staged 64 (bf16), cp.async double buffer, SW128 swizzle.
#define SM_A0 0
#define SM_A1 16384
#define SM_B0 32768
#define SM_B1 49152
#define SM_TOTAL 65536

__device__ __forceinline__ void issueStage(
    uint32_t smb, int aoff, int boff, int tid,
    const __nv_bfloat16* __restrict__ As, const __nv_bfloat16* __restrict__ Bs,
    int ldka, int ldkb, int kk)
{
#pragma unroll
    for (int i = 0; i < 4; i++) {
        int idx = tid + i * 256;
        int r = idx >> 3, ch = idx & 7;
        const void* ga = As + (size_t)r * ldka + kk + ch * 8;
        uint32_t sa = smb + aoff + SW128(r * 128 + ch * 16);
        asm volatile("cp.async.cg.shared.global [%0], [%1], 16;" :: "r"(sa), "l"(ga));
        const void* gb = Bs + (size_t)r * ldkb + kk + ch * 8;
        uint32_t sb = smb + boff + SW128(r * 128 + ch * 16);
        asm volatile("cp.async.cg.shared.global [%0], [%1], 16;" :: "r"(sb), "l"(gb));
    }
}

__global__ void __launch_bounds__(256) kGemmMMA(
    const __nv_bfloat16* __restrict__ Ahi, const __nv_bfloat16* __restrict__ Alo, int ldka,
    const __nv_bfloat16* __restrict__ Bhi, const __nv_bfloat16* __restrict__ Blo,
    int ldkb, long strideB,
    float* __restrict__ C, long strideC, long strideCz, int Kseg)
{
    extern __shared__ char sm[];
    const uint32_t smb = s2u(sm);
    const int tid = threadIdx.x, lane = tid & 31, wid = tid >> 5;
    const int wm = wid >> 2, wn = wid & 3;
    const int row0 = blockIdx.x * 128, b = blockIdx.y, kz = blockIdx.z;
    const int kbase = kz * Kseg;

    const __nv_bfloat16* Ah = Ahi + (size_t)row0 * ldka;
    const __nv_bfloat16* Al = Alo + (size_t)row0 * ldka;
    const __nv_bfloat16* Bh = Bhi + (size_t)b * strideB;
    const __nv_bfloat16* Bl = Blo + (size_t)b * strideB;
    float* Cb = C + (size_t)kz * strideCz + (size_t)b * strideC + (size_t)row0 * 128;

    const int spseg = Kseg / 64;
    const int S = spseg * 3;

    float acc[4][4][4];
#pragma unroll
    for (int i = 0; i < 4; i++)
#pragma unroll
        for (int j = 0; j < 4; j++)
#pragma unroll
            for (int q = 0; q < 4; q++) acc[i][j][q] = 0.f;

    auto segPtrs = [&](int s, const __nv_bfloat16*& As, const __nv_bfloat16*& Bs, int& kk) {
        int seg = s / spseg;
        kk = kbase + (s - seg * spseg) * 64;
        As = (seg < 2) ? Ah : Al;
        Bs = (seg == 1) ? Bl : Bh;
    };

    {   // prefetch stage 0
        const __nv_bfloat16 *As, *Bs; int kk;
        segPtrs(0, As, Bs, kk);
        issueStage(smb, SM_A0, SM_B0, tid, As, Bs, ldka, ldkb, kk);
        asm volatile("cp.async.commit_group;" ::: "memory");
    }

    for (int s = 0; s < S; s++) {
        int buf = s & 1;
        if (s + 1 < S) {
            const __nv_bfloat16 *As, *Bs; int kk;
            segPtrs(s + 1, As, Bs, kk);
            int nb = (s + 1) & 1;
            issueStage(smb, nb ? SM_A1 : SM_A0, nb ? SM_B1 : SM_B0, tid,
                       As, Bs, ldka, ldkb, kk);
            asm volatile("cp.async.commit_group;" ::: "memory");
            asm volatile("cp.async.wait_group 1;" ::: "memory");
        } else {
            asm volatile("cp.async.wait_group 0;" ::: "memory");
        }
        __syncthreads();

        const uint32_t aB = smb + (buf ? SM_A1 : SM_A0);
        const uint32_t bB = smb + (buf ? SM_B1 : SM_B0);
#pragma unroll
        for (int ks = 0; ks < 4; ks++) {
            uint32_t a[4][4], bfr[4][2];
            int kc16 = (ks * 2 + (lane >> 4)) * 16;
            int rA = wm * 64 + (lane & 15);
#pragma unroll
            for (int mi = 0; mi < 4; mi++) {
                uint32_t ad = aB + SW128((rA + mi * 16) * 128 + kc16);
                LDSM4(a[mi][0], a[mi][1], a[mi][2], a[mi][3], ad);
            }
            int rB = wn * 32 + (lane & 15);
#pragma unroll
            for (int nj = 0; nj < 2; nj++) {
                uint32_t r0, r1, r2, r3;
                uint32_t bd = bB + SW128((rB + nj * 16) * 128 + kc16);
                LDSM4(r0, r1, r2, r3, bd);
                bfr[nj * 2][0] = r0; bfr[nj * 2 + 1][0] = r1;
                bfr[nj * 2][1] = r2; bfr[nj * 2 + 1][1] = r3;
            }
#pragma unroll
            for (int mi = 0; mi < 4; mi++)
#pragma unroll
                for (int ni = 0; ni < 4; ni++)
                    MMA16816(acc[mi][ni][0], acc[mi][ni][1], acc[mi][ni][2], acc[mi][ni][3],
                             a[mi][0], a[mi][1], a[mi][2], a[mi][3],
                             bfr[ni][0], bfr[ni][1]);
        }
        __syncthreads();
    }

    // epilogue
    int g = lane >> 2, tg = lane & 3;
#pragma unroll
    for (int mi = 0; mi < 4; mi++)
#pragma unroll
        for (int ni = 0; ni < 4; ni++) {
            int r = wm * 64 + mi * 16 + g;
            int col = wn * 32 + ni * 8 + tg * 2;
            *(float2*)&Cb[(size_t)r * 128 + col] =
                make_float2(acc[mi][ni][0], acc[mi][ni][1]);
            *(float2*)&Cb[(size_t)(r + 8) * 128 + col] =
                make_float2(acc[mi][ni][2], acc[mi][ni][3]);
        }
}

// ---------------- per-mode channel mixing (fp32 SIMT, sums k-partials) --------
// grid (M, 2): each block does 32 b x 64 o for one mode m.
__global__ void __launch_bounds__(256) kMix() {
    __shared__ float xs[32][128];
    __shared__ float ws[16][64];
    int m = blockIdx.x, h = blockIdx.y;
    int t = threadIdx.x;
    const size_t PS = (size_t)B_ * M_ * CI_;
#pragma unroll
    for (int i = 0; i < 4; i++) {
        int idx = i * 256 + t;
        int bb = idx >> 5;
        int cc = (idx & 31) << 2;
        const float* p = &g_xspecP[((size_t)bb * M_ + m) * CI_ + cc];
        float4 v0 = *(const float4*)p;
        float4 v1 = *(const float4*)(p + PS);
        float4 v2 = *(const float4*)(p + 2 * PS);
        float4 v3 = *(const float4*)(p + 3 * PS);
        xs[bb][cc + 0] = v0.x + v1.x + v2.x + v3.x;
        xs[bb][cc + 1] = v0.y + v1.y + v2.y + v3.y;
        xs[bb][cc + 2] = v0.z + v1.z + v2.z + v3.z;
        xs[bb][cc + 3] = v0.w + v1.w + v2.w + v3.w;
    }
    int tx = t & 15, ty = t >> 4;
    unsigned long long acc[2][2];
    acc[0][0] = acc[0][1] = acc[1][0] = acc[1][1] = 0ull;
    const float* Wm = g_Wt + (size_t)m * CI_ * CO_ + h * 64;
    for (int c0 = 0; c0 < CI_; c0 += 16) {
        __syncthreads();
        {
            int cr = t >> 4, oc = (t & 15) << 2;
            *(float4*)&ws[cr][oc] = *(const float4*)&Wm[(size_t)(c0 + cr) * CO_ + oc];
        }
        __syncthreads();
#pragma unroll
        for (int k = 0; k < 16; k++) {
            float4 b4 = *(const float4*)&ws[k][tx << 2];
            unsigned long long b01 = pk2(b4.x, b4.y);
            unsigned long long b23 = pk2(b4.z, b4.w);
#pragma unroll
            for (int i = 0; i < 2; i++) {
                float a = xs[ty * 2 + i][c0 + k];
                unsigned long long ad = pk2(a, a);
                acc[i][0] = ffma2(ad, b01, acc[i][0]);
                acc[i][1] = ffma2(ad, b23, acc[i][1]);
            }
        }
    }
#pragma unroll
    for (int i = 0; i < 2; i++) {
        float4 v;
        upk2(acc[i][0], v.x, v.y);
        upk2(acc[i][1], v.z, v.w);
        int bb = ty * 2 + i;
        *(float4*)&g_ospec[((size_t)bb * M_ + m) * CO_ + h * 64 + (tx << 2)] = v;
    }
}

// ---------------- launch ----------------
extern "C" void kernel_launch(void* const* d_in, const int* in_sizes, int n_in,
                              void* d_out, int out_size) {
    const float* x = (const float*)d_in[0];   // [B, N, C_in]
    const float* U = (const float*)d_in[1];   // [N, M]
    const float* W = (const float*)d_in[2];   // [C_in, C_out, M]
    float* out = (float*)d_out;               // [B, N, C_out]

    float* pXsP;
    __nv_bfloat16 *pUthi, *pUtlo, *pUhi, *pUlo, *pXThi, *pXTlo, *pOThi, *pOTlo;
    cudaGetSymbolAddress((void**)&pXsP, g_xspecP);
    cudaGetSymbolAddress((void**)&pUthi, g_Uthi);
    cudaGetSymbolAddress((void**)&pUtlo, g_Utlo);
    cudaGetSymbolAddress((void**)&pUhi, g_Uhi);
    cudaGetSymbolAddress((void**)&pUlo, g_Ulo);
    cudaGetSymbolAddress((void**)&pXThi, g_xThi);
    cudaGetSymbolAddress((void**)&pXTlo, g_xTlo);
    cudaGetSymbolAddress((void**)&pOThi, g_oThi);
    cudaGetSymbolAddress((void**)&pOTlo, g_oTlo);

    cudaFuncSetAttribute(kGemmMMA, cudaFuncAttributeMaxDynamicSharedMemorySize, SM_TOTAL);

    // prep
    kSplitTransU<<<dim3(M_ / 32, N_ / 32), dim3(32, 8)>>>(U);
    kSplitTransX<<<dim3(N_ / 32, CI_ / 32, B_), dim3(32, 8)>>>(x);
    kTransW<<<dim3(M_ / 32, CO_ / 32, CI_), dim3(32, 8)>>>(W);

    // GEMM1 (K-split x4): xspecP[kz][b][m][c] = sum_{n in split} Ut[m][n]*xT[b][c][n]
    kGemmMMA<<<dim3(M_ / 128, B_, KSPLIT), 256, SM_TOTAL>>>(
        pUthi, pUtlo, N_,
        pXThi, pXTlo, N_, (long)CI_ * N_,
        pXsP, (long)M_ * CI_, (long)B_ * M_ * CI_, N_ / KSPLIT);

    // mixing (sums the 4 partials)
    kMix<<<dim3(M_, 2), 256>>>();
    kSplitTransO<<<dim3(M_ / 32, CO_ / 32, B_), dim3(32, 8)>>>();

    // GEMM2: out[b][n][o] = sum_m U[n][m] * oT[b][o][m]
    kGemmMMA<<<dim3(N_ / 128, B_, 1), 256, SM_TOTAL>>>(
        pUhi, pUlo, M_,
        pOThi, pOTlo, M_, (long)CO_ * M_,
        out, (long)N_ * CO_, 0, M_);
}

// round 4
// speedup vs baseline: 3.0787x; 1.3959x over previous
#include <cuda_runtime.h>
#include <cuda_fp16.h>
#include <cstdint>

#define B_  32
#define N_  4096
#define CI_ 128
#define CO_ 128
#define M_  256
#define KSPLIT 4

// ---------------- device scratch (no allocations allowed) ----------------
__device__ float g_xspecP[(size_t)KSPLIT * B_ * M_ * CI_];  // partial x_spec 16 MB
__device__ float g_ospec[B_ * M_ * CO_];                    // [b][m][o]       4 MB
__device__ float g_Wt[M_ * CI_ * CO_];                      // [m][c][o]      16 MB
__device__ __half g_Uthi[M_ * N_];                          // Ut hi [m][n]
__device__ __half g_Utlo[M_ * N_];
__device__ __half g_Uhi[N_ * M_];                           // U hi [n][m]
__device__ __half g_Ulo[N_ * M_];
__device__ __half g_xT16[(size_t)B_ * CI_ * N_];            // xT fp16 [b][c][n] 32 MB
__device__ __half g_oT16[B_ * CO_ * M_];                    // ospecT fp16 [b][o][m]

// ---------------- helpers ----------------
__device__ __forceinline__ void split2h(float v, __half& h, __half& l) {
    h = __float2half(v);
    l = __float2half(v - __half2float(h));
}
__device__ __forceinline__ uint32_t s2u(const void* p) {
    uint32_t a;
    asm("{ .reg .u64 t; cvta.to.shared.u64 t, %1; cvt.u32.u64 %0, t; }" : "=r"(a) : "l"(p));
    return a;
}
#define SW128(o) ((o) ^ (((o) >> 3) & 0x70))

#define LDSM4(d0, d1, d2, d3, addr)                                                  \
    asm volatile("ldmatrix.sync.aligned.m8n8.x4.shared.b16 {%0,%1,%2,%3}, [%4];"     \
                 : "=r"(d0), "=r"(d1), "=r"(d2), "=r"(d3) : "r"(addr))

#define MMA16816(d0, d1, d2, d3, a0, a1, a2, a3, b0, b1)                             \
    asm volatile("mma.sync.aligned.m16n8k16.row.col.f32.f16.f16.f32 "                \
                 "{%0,%1,%2,%3},{%4,%5,%6,%7},{%8,%9},{%0,%1,%2,%3};"                \
                 : "+f"(d0), "+f"(d1), "+f"(d2), "+f"(d3)                            \
                 : "r"(a0), "r"(a1), "r"(a2), "r"(a3), "r"(b0), "r"(b1))

#define CP_ASYNC16(saddr, gptr) \
    asm volatile("cp.async.cg.shared.global [%0], [%1], 16;" :: "r"(saddr), "l"(gptr))
#define CP_COMMIT() asm volatile("cp.async.commit_group;" ::: "memory")
#define CP_WAIT1()  asm volatile("cp.async.wait_group 1;" ::: "memory")

// packed f32x2 (for kMix)
__device__ __forceinline__ unsigned long long pk2(float lo, float hi) {
    unsigned long long r;
    asm("mov.b64 %0, {%1, %2};" : "=l"(r) : "f"(lo), "f"(hi));
    return r;
}
__device__ __forceinline__ unsigned long long ffma2(unsigned long long a,
                                                    unsigned long long b,
                                                    unsigned long long c) {
    unsigned long long d;
    asm("fma.rn.f32x2 %0, %1, %2, %3;" : "=l"(d) : "l"(a), "l"(b), "l"(c));
    return d;
}
__device__ __forceinline__ void upk2(unsigned long long v, float& lo, float& hi) {
    asm("mov.b64 {%0, %1}, %2;" : "=f"(lo), "=f"(hi) : "l"(v));
}

// ---------------- prep kernels ----------------
__global__ void kSplitTransU(const float* __restrict__ U) {
    __shared__ float tile[32][33];
    int m0 = blockIdx.x * 32, n0 = blockIdx.y * 32;
    int tx = threadIdx.x, ty = threadIdx.y;  // 32 x 8
#pragma unroll
    for (int j = 0; j < 4; j++) {
        int nl = ty + j * 8;
        float v = U[(size_t)(n0 + nl) * M_ + m0 + tx];
        tile[nl][tx] = v;
        __half h, l; split2h(v, h, l);
        g_Uhi[(size_t)(n0 + nl) * M_ + m0 + tx] = h;
        g_Ulo[(size_t)(n0 + nl) * M_ + m0 + tx] = l;
    }
    __syncthreads();
#pragma unroll
    for (int j = 0; j < 4; j++) {
        int ml = ty + j * 8;
        float v = tile[tx][ml];
        __half h, l; split2h(v, h, l);
        g_Uthi[(size_t)(m0 + ml) * N_ + n0 + tx] = h;
        g_Utlo[(size_t)(m0 + ml) * N_ + n0 + tx] = l;
    }
}

// x[b][n][c] fp32 -> xT16[b][c][n] fp16
__global__ void kTransX(const float* __restrict__ x) {
    __shared__ float tile[32][33];
    int n0 = blockIdx.x * 32, c0 = blockIdx.y * 32, b = blockIdx.z;
    int tx = threadIdx.x, ty = threadIdx.y;
    const float* xb = x + (size_t)b * N_ * CI_;
#pragma unroll
    for (int j = 0; j < 4; j++)
        tile[ty + j * 8][tx] = xb[(size_t)(n0 + ty + j * 8) * CI_ + c0 + tx];
    __syncthreads();
    __half* oh = g_xT16 + (size_t)b * CI_ * N_;
#pragma unroll
    for (int j = 0; j < 4; j++) {
        int cl = ty + j * 8;
        oh[(size_t)(c0 + cl) * N_ + n0 + tx] = __float2half(tile[tx][cl]);
    }
}

__global__ void kTransW(const float* __restrict__ W) {
    __shared__ float tile[32][33];
    int m0 = blockIdx.x * 32, o0 = blockIdx.y * 32, c = blockIdx.z;
    int tx = threadIdx.x, ty = threadIdx.y;
    const float* Wc = W + (size_t)c * CO_ * M_;
#pragma unroll
    for (int j = 0; j < 4; j++)
        tile[ty + j * 8][tx] = Wc[(size_t)(o0 + ty + j * 8) * M_ + m0 + tx];
    __syncthreads();
#pragma unroll
    for (int j = 0; j < 4; j++)
        g_Wt[(size_t)(m0 + ty + j * 8) * CI_ * CO_ + (size_t)c * CO_ + o0 + tx] =
            tile[tx][ty + j * 8];
}

// ospec[b][m][o] fp32 -> oT16[b][o][m] fp16
__global__ void kTransO() {
    __shared__ float tile[32][33];
    int m0 = blockIdx.x * 32, o0 = blockIdx.y * 32, b = blockIdx.z;
    int tx = threadIdx.x, ty = threadIdx.y;
    const float* ob = g_ospec + (size_t)b * M_ * CO_;
#pragma unroll
    for (int j = 0; j < 4; j++)
        tile[ty + j * 8][tx] = ob[(size_t)(m0 + ty + j * 8) * CO_ + o0 + tx];
    __syncthreads();
    __half* oh = g_oT16 + (size_t)b * CO_ * M_;
#pragma unroll
    for (int j = 0; j < 4; j++) {
        int olc = ty + j * 8;
        oh[(size_t)(o0 + olc) * M_ + m0 + tx] = __float2half(tile[tx][olc]);
    }
}

// ---------------- 2-pass split-fp16 TN GEMM via mma.sync ----------------
// D[row][col] = sum_k (Ahi+Alo)[row][k] * B[col][k]
// 128x128 CTA tile, 8 warps 2x4 (warp tile 64x32), K staged 64,
// 3-stage cp.async ring, stage = {Ahi 16K, Alo 16K, B 16K} = 48K.
#define STG_BYTES 49152
#define SM_TOTAL  (3 * STG_BYTES)

__device__ __forceinline__ void issueStage(
    uint32_t smb, int off, int tid,
    const __half* __restrict__ Ah, const __half* __restrict__ Al,
    const __half* __restrict__ Bs, int ldka, int ldkb, int kk)
{
#pragma unroll
    for (int i = 0; i < 4; i++) {
        int idx = tid + i * 256;
        int r = idx >> 3, ch = idx & 7;
        int sw = SW128(r * 128 + ch * 16);
        CP_ASYNC16(smb + off + sw,           Ah + (size_t)r * ldka + kk + ch * 8);
        CP_ASYNC16(smb + off + 16384 + sw,   Al + (size_t)r * ldka + kk + ch * 8);
        CP_ASYNC16(smb + off + 32768 + sw,   Bs + (size_t)r * ldkb + kk + ch * 8);
    }
}

__global__ void __launch_bounds__(256) kGemmMMA(
    const __half* __restrict__ Ahi, const __half* __restrict__ Alo, int ldka,
    const __half* __restrict__ B16, int ldkb, long strideB,
    float* __restrict__ C, long strideC, long strideCz, int Kseg)
{
    extern __shared__ char sm[];
    const uint32_t smb = s2u(sm);
    const int tid = threadIdx.x, lane = tid & 31, wid = tid >> 5;
    const int wm = wid >> 2, wn = wid & 3;
    const int row0 = blockIdx.x * 128, b = blockIdx.y, kz = blockIdx.z;
    const int kbase = kz * Kseg;

    const __half* Ah = Ahi + (size_t)row0 * ldka;
    const __half* Al = Alo + (size_t)row0 * ldka;
    const __half* Bb = B16 + (size_t)b * strideB;
    float* Cb = C + (size_t)kz * strideCz + (size_t)b * strideC + (size_t)row0 * 128;

    const int S = Kseg / 64;

    float acc[4][4][4];
#pragma unroll
    for (int i = 0; i < 4; i++)
#pragma unroll
        for (int j = 0; j < 4; j++)
#pragma unroll
            for (int q = 0; q < 4; q++) acc[i][j][q] = 0.f;

    // prologue: stages 0 and 1
    issueStage(smb, 0, tid, Ah, Al, Bb, ldka, ldkb, kbase);
    CP_COMMIT();
    issueStage(smb, STG_BYTES, tid, Ah, Al, Bb, ldka, ldkb, kbase + 64);
    CP_COMMIT();

    for (int s = 0; s < S; s++) {
        CP_WAIT1();
        __syncthreads();
        if (s + 2 < S)
            issueStage(smb, ((s + 2) % 3) * STG_BYTES, tid, Ah, Al, Bb,
                       ldka, ldkb, kbase + (s + 2) * 64);
        CP_COMMIT();

        const uint32_t stB = smb + (s % 3) * STG_BYTES;
        const uint32_t aHiB = stB, aLoB = stB + 16384, bBB = stB + 32768;
#pragma unroll
        for (int ks = 0; ks < 4; ks++) {
            int kc16 = (ks * 2 + (lane >> 4)) * 16;
            uint32_t ah[4][4], al[4][4], bfr[4][2];
            int rB = wn * 32 + (lane & 15);
#pragma unroll
            for (int nj = 0; nj < 2; nj++) {
                uint32_t r0, r1, r2, r3;
                LDSM4(r0, r1, r2, r3, bBB + SW128((rB + nj * 16) * 128 + kc16));
                bfr[nj * 2][0] = r0; bfr[nj * 2 + 1][0] = r1;
                bfr[nj * 2][1] = r2; bfr[nj * 2 + 1][1] = r3;
            }
            int rA = wm * 64 + (lane & 15);
#pragma unroll
            for (int mi = 0; mi < 4; mi++)
                LDSM4(ah[mi][0], ah[mi][1], ah[mi][2], ah[mi][3],
                      aHiB + SW128((rA + mi * 16) * 128 + kc16));
#pragma unroll
            for (int mi = 0; mi < 4; mi++)
                LDSM4(al[mi][0], al[mi][1], al[mi][2], al[mi][3],
                      aLoB + SW128((rA + mi * 16) * 128 + kc16));
#pragma unroll
            for (int mi = 0; mi < 4; mi++)
#pragma unroll
                for (int ni = 0; ni < 4; ni++)
                    MMA16816(acc[mi][ni][0], acc[mi][ni][1], acc[mi][ni][2], acc[mi][ni][3],
                             ah[mi][0], ah[mi][1], ah[mi][2], ah[mi][3],
                             bfr[ni][0], bfr[ni][1]);
#pragma unroll
            for (int mi = 0; mi < 4; mi++)
#pragma unroll
                for (int ni = 0; ni < 4; ni++)
                    MMA16816(acc[mi][ni][0], acc[mi][ni][1], acc[mi][ni][2], acc[mi][ni][3],
                             al[mi][0], al[mi][1], al[mi][2], al[mi][3],
                             bfr[ni][0], bfr[ni][1]);
        }
        __syncthreads();
    }

    // epilogue
    int g = lane >> 2, tg = lane & 3;
#pragma unroll
    for (int mi = 0; mi < 4; mi++)
#pragma unroll
        for (int ni = 0; ni < 4; ni++) {
            int r = wm * 64 + mi * 16 + g;
            int col = wn * 32 + ni * 8 + tg * 2;
            *(float2*)&Cb[(size_t)r * 128 + col] =
                make_float2(acc[mi][ni][0], acc[mi][ni][1]);
            *(float2*)&Cb[(size_t)(r + 8) * 128 + col] =
                make_float2(acc[mi][ni][2], acc[mi][ni][3]);
        }
}

// ---------------- per-mode channel mixing (fp32 SIMT, sums k-partials) --------
__global__ void __launch_bounds__(256) kMix() {
    __shared__ float xs[32][128];
    __shared__ float ws[16][64];
    int m = blockIdx.x, h = blockIdx.y;
    int t = threadIdx.x;
    const size_t PS = (size_t)B_ * M_ * CI_;
#pragma unroll
    for (int i = 0; i < 4; i++) {
        int idx = i * 256 + t;
        int bb = idx >> 5;
        int cc = (idx & 31) << 2;
        const float* p = &g_xspecP[((size_t)bb * M_ + m) * CI_ + cc];
        float4 v0 = *(const float4*)p;
        float4 v1 = *(const float4*)(p + PS);
        float4 v2 = *(const float4*)(p + 2 * PS);
        float4 v3 = *(const float4*)(p + 3 * PS);
        xs[bb][cc + 0] = v0.x + v1.x + v2.x + v3.x;
        xs[bb][cc + 1] = v0.y + v1.y + v2.y + v3.y;
        xs[bb][cc + 2] = v0.z + v1.z + v2.z + v3.z;
        xs[bb][cc + 3] = v0.w + v1.w + v2.w + v3.w;
    }
    int tx = t & 15, ty = t >> 4;
    unsigned long long acc[2][2];
    acc[0][0] = acc[0][1] = acc[1][0] = acc[1][1] = 0ull;
    const float* Wm = g_Wt + (size_t)m * CI_ * CO_ + h * 64;
    for (int c0 = 0; c0 < CI_; c0 += 16) {
        __syncthreads();
        {
            int cr = t >> 4, oc = (t & 15) << 2;
            *(float4*)&ws[cr][oc] = *(const float4*)&Wm[(size_t)(c0 + cr) * CO_ + oc];
        }
        __syncthreads();
#pragma unroll
        for (int k = 0; k < 16; k++) {
            float4 b4 = *(const float4*)&ws[k][tx << 2];
            unsigned long long b01 = pk2(b4.x, b4.y);
            unsigned long long b23 = pk2(b4.z, b4.w);
#pragma unroll
            for (int i = 0; i < 2; i++) {
                float a = xs[ty * 2 + i][c0 + k];
                unsigned long long ad = pk2(a, a);
                acc[i][0] = ffma2(ad, b01, acc[i][0]);
                acc[i][1] = ffma2(ad, b23, acc[i][1]);
            }
        }
    }
#pragma unroll
    for (int i = 0; i < 2; i++) {
        float4 v;
        upk2(acc[i][0], v.x, v.y);
        upk2(acc[i][1], v.z, v.w);
        int bb = ty * 2 + i;
        *(float4*)&g_ospec[((size_t)bb * M_ + m) * CO_ + h * 64 + (tx << 2)] = v;
    }
}

// ---------------- launch ----------------
extern "C" void kernel_launch(void* const* d_in, const int* in_sizes, int n_in,
                              void* d_out, int out_size) {
    const float* x = (const float*)d_in[0];   // [B, N, C_in]
    const float* U = (const float*)d_in[1];   // [N, M]
    const float* W = (const float*)d_in[2];   // [C_in, C_out, M]
    float* out = (float*)d_out;               // [B, N, C_out]

    float* pXsP;
    __half *pUthi, *pUtlo, *pUhi, *pUlo, *pXT, *pOT;
    cudaGetSymbolAddress((void**)&pXsP, g_xspecP);
    cudaGetSymbolAddress((void**)&pUthi, g_Uthi);
    cudaGetSymbolAddress((void**)&pUtlo, g_Utlo);
    cudaGetSymbolAddress((void**)&pUhi, g_Uhi);
    cudaGetSymbolAddress((void**)&pUlo, g_Ulo);
    cudaGetSymbolAddress((void**)&pXT, g_xT16);
    cudaGetSymbolAddress((void**)&pOT, g_oT16);

    cudaFuncSetAttribute(kGemmMMA, cudaFuncAttributeMaxDynamicSharedMemorySize, SM_TOTAL);

    // prep
    kSplitTransU<<<dim3(M_ / 32, N_ / 32), dim3(32, 8)>>>(U);
    kTransX<<<dim3(N_ / 32, CI_ / 32, B_), dim3(32, 8)>>>(x);
    kTransW<<<dim3(M_ / 32, CO_ / 32, CI_), dim3(32, 8)>>>(W);

    // GEMM1 (K-split x4): xspecP[kz][b][m][c] = sum_n Ut[m][n] * xT[b][c][n]
    kGemmMMA<<<dim3(M_ / 128, B_, KSPLIT), 256, SM_TOTAL>>>(
        pUthi, pUtlo, N_,
        pXT, N_, (long)CI_ * N_,
        pXsP, (long)M_ * CI_, (long)B_ * M_ * CI_, N_ / KSPLIT);

    // mixing (sums the 4 partials) + transpose to fp16
    kMix<<<dim3(M_, 2), 256>>>();
    kTransO<<<dim3(M_ / 32, CO_ / 32, B_), dim3(32, 8)>>>();

    // GEMM2: out[b][n][o] = sum_m U[n][m] * oT[b][o][m]
    kGemmMMA<<<dim3(N_ / 128, B_, 1), 256, SM_TOTAL>>>(
        pUhi, pUlo, M_,
        pOT, M_, (long)CO_ * M_,
        out, (long)N_ * CO_, 0, M_);
}

// round 5
// speedup vs baseline: 3.2633x; 1.0600x over previous
#include <cuda_runtime.h>
#include <cuda_fp16.h>
#include <cstdint>

#define B_  32
#define N_  4096
#define CI_ 128
#define CO_ 128
#define M_  256
#define KSPLIT 9
#define KSEG0  448   // 7 x 64; last split gets 512 = 8 x 64

// ---------------- device scratch (no allocations allowed) ----------------
__device__ float g_xspecP[(size_t)KSPLIT * B_ * M_ * CI_];  // partial x_spec 36 MB
__device__ float g_ospec[B_ * M_ * CO_];                    // [b][m][o]
__device__ float g_Wt[M_ * CI_ * CO_];                      // [m][c][o]
__device__ __half g_Uthi[M_ * N_];                          // Ut hi [m][n]
__device__ __half g_Utlo[M_ * N_];
__device__ __half g_Uhi[N_ * M_];                           // U hi [n][m]
__device__ __half g_Ulo[N_ * M_];
__device__ __half g_xT16[(size_t)B_ * CI_ * N_];            // xT fp16 [b][c][n]
__device__ __half g_oT16[B_ * CO_ * M_];                    // ospecT fp16 [b][o][m]

// ---------------- helpers ----------------
__device__ __forceinline__ void split2h(float v, __half& h, __half& l) {
    h = __float2half(v);
    l = __float2half(v - __half2float(h));
}
__device__ __forceinline__ uint32_t s2u(const void* p) {
    uint32_t a;
    asm("{ .reg .u64 t; cvta.to.shared.u64 t, %1; cvt.u32.u64 %0, t; }" : "=r"(a) : "l"(p));
    return a;
}
#define SW128(o) ((o) ^ (((o) >> 3) & 0x70))

#define LDSM4(d0, d1, d2, d3, addr)                                                  \
    asm volatile("ldmatrix.sync.aligned.m8n8.x4.shared.b16 {%0,%1,%2,%3}, [%4];"     \
                 : "=r"(d0), "=r"(d1), "=r"(d2), "=r"(d3) : "r"(addr))

#define MMA16816(d0, d1, d2, d3, a0, a1, a2, a3, b0, b1)                             \
    asm volatile("mma.sync.aligned.m16n8k16.row.col.f32.f16.f16.f32 "                \
                 "{%0,%1,%2,%3},{%4,%5,%6,%7},{%8,%9},{%0,%1,%2,%3};"                \
                 : "+f"(d0), "+f"(d1), "+f"(d2), "+f"(d3)                            \
                 : "r"(a0), "r"(a1), "r"(a2), "r"(a3), "r"(b0), "r"(b1))

#define CP_ASYNC16(saddr, gptr) \
    asm volatile("cp.async.cg.shared.global [%0], [%1], 16;" :: "r"(saddr), "l"(gptr))
#define CP_COMMIT() asm volatile("cp.async.commit_group;" ::: "memory")
#define CP_WAIT1()  asm volatile("cp.async.wait_group 1;" ::: "memory")

// packed f32x2 (for kMix)
__device__ __forceinline__ unsigned long long pk2(float lo, float hi) {
    unsigned long long r;
    asm("mov.b64 %0, {%1, %2};" : "=l"(r) : "f"(lo), "f"(hi));
    return r;
}
__device__ __forceinline__ unsigned long long ffma2(unsigned long long a,
                                                    unsigned long long b,
                                                    unsigned long long c) {
    unsigned long long d;
    asm("fma.rn.f32x2 %0, %1, %2, %3;" : "=l"(d) : "l"(a), "l"(b), "l"(c));
    return d;
}
__device__ __forceinline__ void upk2(unsigned long long v, float& lo, float& hi) {
    asm("mov.b64 {%0, %1}, %2;" : "=f"(lo), "=f"(hi) : "l"(v));
}

// ---------------- prep kernels ----------------
__global__ void kSplitTransU(const float* __restrict__ U) {
    __shared__ float tile[32][33];
    int m0 = blockIdx.x * 32, n0 = blockIdx.y * 32;
    int tx = threadIdx.x, ty = threadIdx.y;  // 32 x 8
#pragma unroll
    for (int j = 0; j < 4; j++) {
        int nl = ty + j * 8;
        float v = U[(size_t)(n0 + nl) * M_ + m0 + tx];
        tile[nl][tx] = v;
        __half h, l; split2h(v, h, l);
        g_Uhi[(size_t)(n0 + nl) * M_ + m0 + tx] = h;
        g_Ulo[(size_t)(n0 + nl) * M_ + m0 + tx] = l;
    }
    __syncthreads();
#pragma unroll
    for (int j = 0; j < 4; j++) {
        int ml = ty + j * 8;
        float v = tile[tx][ml];
        __half h, l; split2h(v, h, l);
        g_Uthi[(size_t)(m0 + ml) * N_ + n0 + tx] = h;
        g_Utlo[(size_t)(m0 + ml) * N_ + n0 + tx] = l;
    }
}

// x[b][n][c] fp32 -> xT16[b][c][n] fp16
__global__ void kTransX(const float* __restrict__ x) {
    __shared__ float tile[32][33];
    int n0 = blockIdx.x * 32, c0 = blockIdx.y * 32, b = blockIdx.z;
    int tx = threadIdx.x, ty = threadIdx.y;
    const float* xb = x + (size_t)b * N_ * CI_;
#pragma unroll
    for (int j = 0; j < 4; j++)
        tile[ty + j * 8][tx] = xb[(size_t)(n0 + ty + j * 8) * CI_ + c0 + tx];
    __syncthreads();
    __half* oh = g_xT16 + (size_t)b * CI_ * N_;
#pragma unroll
    for (int j = 0; j < 4; j++) {
        int cl = ty + j * 8;
        oh[(size_t)(c0 + cl) * N_ + n0 + tx] = __float2half(tile[tx][cl]);
    }
}

__global__ void kTransW(const float* __restrict__ W) {
    __shared__ float tile[32][33];
    int m0 = blockIdx.x * 32, o0 = blockIdx.y * 32, c = blockIdx.z;
    int tx = threadIdx.x, ty = threadIdx.y;
    const float* Wc = W + (size_t)c * CO_ * M_;
#pragma unroll
    for (int j = 0; j < 4; j++)
        tile[ty + j * 8][tx] = Wc[(size_t)(o0 + ty + j * 8) * M_ + m0 + tx];
    __syncthreads();
#pragma unroll
    for (int j = 0; j < 4; j++)
        g_Wt[(size_t)(m0 + ty + j * 8) * CI_ * CO_ + (size_t)c * CO_ + o0 + tx] =
            tile[tx][ty + j * 8];
}

// ospec[b][m][o] fp32 -> oT16[b][o][m] fp16
__global__ void kTransO() {
    __shared__ float tile[32][33];
    int m0 = blockIdx.x * 32, o0 = blockIdx.y * 32, b = blockIdx.z;
    int tx = threadIdx.x, ty = threadIdx.y;
    const float* ob = g_ospec + (size_t)b * M_ * CO_;
#pragma unroll
    for (int j = 0; j < 4; j++)
        tile[ty + j * 8][tx] = ob[(size_t)(m0 + ty + j * 8) * CO_ + o0 + tx];
    __syncthreads();
    __half* oh = g_oT16 + (size_t)b * CO_ * M_;
#pragma unroll
    for (int j = 0; j < 4; j++) {
        int olc = ty + j * 8;
        oh[(size_t)(o0 + olc) * M_ + m0 + tx] = __float2half(tile[tx][olc]);
    }
}

// ---------------- 2-pass split-fp16 TN GEMM, 128x256 tile (batch-paired) ------
// D[row][b-pair col] = sum_k (Ahi+Alo)[row][k] * B[b][col][k]
// 512 threads = 16 warps (2 x 8), warp tile 64x32.
// Stage: Ahi 16K | Alo 16K | B 32K (two batches' 128-col tiles) = 64 KB.
#define STG_BYTES 65536
#define SM_TOTAL  (3 * STG_BYTES)

__device__ __forceinline__ void issueStage(
    uint32_t smb, int off, int tid,
    const __half* __restrict__ Ah, const __half* __restrict__ Al,
    const __half* __restrict__ Bb, long strideB, int ldka, int ldkb, int kk)
{
#pragma unroll
    for (int i = 0; i < 4; i++) {   // A: 2048 chunks (hi 1024 + lo 1024)
        int idx = tid + i * 512;
        int r = idx >> 3, ch = idx & 7;
        const __half* src = (r < 128) ? (Ah + (size_t)r * ldka)
                                      : (Al + (size_t)(r - 128) * ldka);
        int sw = SW128((r & 127) * 128 + ch * 16);
        CP_ASYNC16(smb + off + ((r < 128) ? 0 : 16384) + sw, src + kk + ch * 8);
    }
#pragma unroll
    for (int i = 0; i < 4; i++) {   // B: 2048 chunks (256 rows x 128B)
        int idx = tid + i * 512;
        int rb = idx >> 3, ch = idx & 7;
        const __half* src = Bb + ((rb >= 128) ? strideB : 0)
                            + (size_t)(rb & 127) * ldkb + kk + ch * 8;
        CP_ASYNC16(smb + off + 32768 + SW128(rb * 128 + ch * 16), src);
    }
}

__global__ void __launch_bounds__(512, 1) kGemmMMA(
    const __half* __restrict__ Ahi, const __half* __restrict__ Alo, int ldka,
    const __half* __restrict__ B16, int ldkb, long strideB,
    float* __restrict__ C, long strideC, long strideCz, int kseg0, int Ktot)
{
    extern __shared__ char sm[];
    const uint32_t smb = s2u(sm);
    const int tid = threadIdx.x, lane = tid & 31, wid = tid >> 5;
    const int wm = wid >> 3, wn = wid & 7;
    const int row0 = blockIdx.x * 128, bp = blockIdx.y, kz = blockIdx.z;
    const int kbase = kz * kseg0;
    const int Kseg = (kz == gridDim.z - 1) ? (Ktot - kbase) : kseg0;

    const __half* Ah = Ahi + (size_t)row0 * ldka;
    const __half* Al = Alo + (size_t)row0 * ldka;
    const __half* Bb = B16 + (size_t)(2 * bp) * strideB;
    float* Cb0 = C + (size_t)kz * strideCz + (size_t)(2 * bp) * strideC
                 + (size_t)row0 * 128;

    const int S = Kseg / 64;

    float acc[4][4][4];
#pragma unroll
    for (int i = 0; i < 4; i++)
#pragma unroll
        for (int j = 0; j < 4; j++)
#pragma unroll
            for (int q = 0; q < 4; q++) acc[i][j][q] = 0.f;

    issueStage(smb, 0, tid, Ah, Al, Bb, strideB, ldka, ldkb, kbase);
    CP_COMMIT();
    issueStage(smb, STG_BYTES, tid, Ah, Al, Bb, strideB, ldka, ldkb, kbase + 64);
    CP_COMMIT();

    for (int s = 0; s < S; s++) {
        CP_WAIT1();
        __syncthreads();
        if (s + 2 < S)
            issueStage(smb, ((s + 2) % 3) * STG_BYTES, tid, Ah, Al, Bb, strideB,
                       ldka, ldkb, kbase + (s + 2) * 64);
        CP_COMMIT();

        const uint32_t stB = smb + (s % 3) * STG_BYTES;
        const uint32_t aHiB = stB, aLoB = stB + 16384, bBB = stB + 32768;
#pragma unroll
        for (int ks = 0; ks < 4; ks++) {
            int kc16 = (ks * 2 + (lane >> 4)) * 16;
            uint32_t ah[4][4], al[4][4], bfr[4][2];
            int rB = wn * 32 + (lane & 15);
#pragma unroll
            for (int nj = 0; nj < 2; nj++) {
                uint32_t r0, r1, r2, r3;
                LDSM4(r0, r1, r2, r3, bBB + SW128((rB + nj * 16) * 128 + kc16));
                bfr[nj * 2][0] = r0; bfr[nj * 2 + 1][0] = r1;
                bfr[nj * 2][1] = r2; bfr[nj * 2 + 1][1] = r3;
            }
            int rA = wm * 64 + (lane & 15);
#pragma unroll
            for (int mi = 0; mi < 4; mi++)
                LDSM4(ah[mi][0], ah[mi][1], ah[mi][2], ah[mi][3],
                      aHiB + SW128((rA + mi * 16) * 128 + kc16));
#pragma unroll
            for (int mi = 0; mi < 4; mi++)
                LDSM4(al[mi][0], al[mi][1], al[mi][2], al[mi][3],
                      aLoB + SW128((rA + mi * 16) * 128 + kc16));
#pragma unroll
            for (int mi = 0; mi < 4; mi++)
#pragma unroll
                for (int ni = 0; ni < 4; ni++)
                    MMA16816(acc[mi][ni][0], acc[mi][ni][1], acc[mi][ni][2], acc[mi][ni][3],
                             ah[mi][0], ah[mi][1], ah[mi][2], ah[mi][3],
                             bfr[ni][0], bfr[ni][1]);
#pragma unroll
            for (int mi = 0; mi < 4; mi++)
#pragma unroll
                for (int ni = 0; ni < 4; ni++)
                    MMA16816(acc[mi][ni][0], acc[mi][ni][1], acc[mi][ni][2], acc[mi][ni][3],
                             al[mi][0], al[mi][1], al[mi][2], al[mi][3],
                             bfr[ni][0], bfr[ni][1]);
        }
        __syncthreads();
    }

    // epilogue: warp's 32 cols live in one batch half (wn<4 -> b0, else b1)
    float* Cb = Cb0 + ((wn >= 4) ? strideC : 0);
    int g = lane >> 2, tg = lane & 3;
#pragma unroll
    for (int mi = 0; mi < 4; mi++)
#pragma unroll
        for (int ni = 0; ni < 4; ni++) {
            int r = wm * 64 + mi * 16 + g;
            int col = (wn * 32 + ni * 8 + tg * 2) & 127;
            *(float2*)&Cb[(size_t)r * 128 + col] =
                make_float2(acc[mi][ni][0], acc[mi][ni][1]);
            *(float2*)&Cb[(size_t)(r + 8) * 128 + col] =
                make_float2(acc[mi][ni][2], acc[mi][ni][3]);
        }
}

// ---------------- per-mode channel mixing (fp32 SIMT, sums KSPLIT partials) ---
__global__ void __launch_bounds__(256) kMix() {
    __shared__ float xs[32][128];
    __shared__ float ws[16][64];
    int m = blockIdx.x, h = blockIdx.y;
    int t = threadIdx.x;
    const size_t PS = (size_t)B_ * M_ * CI_;
#pragma unroll
    for (int i = 0; i < 4; i++) {
        int idx = i * 256 + t;
        int bb = idx >> 5;
        int cc = (idx & 31) << 2;
        const float* p = &g_xspecP[((size_t)bb * M_ + m) * CI_ + cc];
        float4 a = *(const float4*)p;
#pragma unroll
        for (int z = 1; z < KSPLIT; z++) {
            float4 v = *(const float4*)(p + (size_t)z * PS);
            a.x += v.x; a.y += v.y; a.z += v.z; a.w += v.w;
        }
        *(float4*)&xs[bb][cc] = a;
    }
    int tx = t & 15, ty = t >> 4;
    unsigned long long acc[2][2];
    acc[0][0] = acc[0][1] = acc[1][0] = acc[1][1] = 0ull;
    const float* Wm = g_Wt + (size_t)m * CI_ * CO_ + h * 64;
    for (int c0 = 0; c0 < CI_; c0 += 16) {
        __syncthreads();
        {
            int cr = t >> 4, oc = (t & 15) << 2;
            *(float4*)&ws[cr][oc] = *(const float4*)&Wm[(size_t)(c0 + cr) * CO_ + oc];
        }
        __syncthreads();
#pragma unroll
        for (int k = 0; k < 16; k++) {
            float4 b4 = *(const float4*)&ws[k][tx << 2];
            unsigned long long b01 = pk2(b4.x, b4.y);
            unsigned long long b23 = pk2(b4.z, b4.w);
#pragma unroll
            for (int i = 0; i < 2; i++) {
                float a = xs[ty * 2 + i][c0 + k];
                unsigned long long ad = pk2(a, a);
                acc[i][0] = ffma2(ad, b01, acc[i][0]);
                acc[i][1] = ffma2(ad, b23, acc[i][1]);
            }
        }
    }
#pragma unroll
    for (int i = 0; i < 2; i++) {
        float4 v;
        upk2(acc[i][0], v.x, v.y);
        upk2(acc[i][1], v.z, v.w);
        int bb = ty * 2 + i;
        *(float4*)&g_ospec[((size_t)bb * M_ + m) * CO_ + h * 64 + (tx << 2)] = v;
    }
}

// ---------------- launch ----------------
extern "C" void kernel_launch(void* const* d_in, const int* in_sizes, int n_in,
                              void* d_out, int out_size) {
    const float* x = (const float*)d_in[0];   // [B, N, C_in]
    const float* U = (const float*)d_in[1];   // [N, M]
    const float* W = (const float*)d_in[2];   // [C_in, C_out, M]
    float* out = (float*)d_out;               // [B, N, C_out]

    float* pXsP;
    __half *pUthi, *pUtlo, *pUhi, *pUlo, *pXT, *pOT;
    cudaGetSymbolAddress((void**)&pXsP, g_xspecP);
    cudaGetSymbolAddress((void**)&pUthi, g_Uthi);
    cudaGetSymbolAddress((void**)&pUtlo, g_Utlo);
    cudaGetSymbolAddress((void**)&pUhi, g_Uhi);
    cudaGetSymbolAddress((void**)&pUlo, g_Ulo);
    cudaGetSymbolAddress((void**)&pXT, g_xT16);
    cudaGetSymbolAddress((void**)&pOT, g_oT16);

    cudaFuncSetAttribute(kGemmMMA, cudaFuncAttributeMaxDynamicSharedMemorySize, SM_TOTAL);

    // prep
    kSplitTransU<<<dim3(M_ / 32, N_ / 32), dim3(32, 8)>>>(U);
    kTransX<<<dim3(N_ / 32, CI_ / 32, B_), dim3(32, 8)>>>(x);
    kTransW<<<dim3(M_ / 32, CO_ / 32, CI_), dim3(32, 8)>>>(W);

    // GEMM1 (K-split x9): xspecP[kz][b][m][c] = sum_n Ut[m][n] * xT[b][c][n]
    kGemmMMA<<<dim3(M_ / 128, B_ / 2, KSPLIT), 512, SM_TOTAL>>>(
        pUthi, pUtlo, N_,
        pXT, N_, (long)CI_ * N_,
        pXsP, (long)M_ * CI_, (long)B_ * M_ * CI_, KSEG0, N_);

    // mixing (sums the 9 partials) + transpose to fp16
    kMix<<<dim3(M_, 2), 256>>>();
    kTransO<<<dim3(M_ / 32, CO_ / 32, B_), dim3(32, 8)>>>();

    // GEMM2: out[b][n][o] = sum_m U[n][m] * oT[b][o][m]
    kGemmMMA<<<dim3(N_ / 128, B_ / 2, 1), 512, SM_TOTAL>>>(
        pUhi, pUlo, M_,
        pOT, M_, (long)CO_ * M_,
        out, (long)N_ * CO_, 0, M_, M_);
}

// round 6
// speedup vs baseline: 4.2357x; 1.2980x over previous
#include <cuda_runtime.h>
#include <cuda_fp16.h>
#include <cstdint>

#define B_  32
#define N_  4096
#define CI_ 128
#define CO_ 128
#define M_  256
#define KSPLIT 9
#define KSEG0  448   // 7 x 64; last split gets 512 = 8 x 64

// ---------------- device scratch (no allocations allowed) ----------------
__device__ float g_xspecP[(size_t)KSPLIT * B_ * M_ * CI_];  // partial x_spec 36 MB
__device__ float g_ospec[B_ * M_ * CO_];                    // [b][m][o]
__device__ float g_Wt[M_ * CI_ * CO_];                      // [m][c][o]
__device__ __half g_Ut16[M_ * N_];                          // Ut fp16 [m][n]
__device__ __half g_U16[N_ * M_];                           // U  fp16 [n][m]
__device__ __half g_xT16[(size_t)B_ * CI_ * N_];            // xT fp16 [b][c][n]
__device__ __half g_oT16[B_ * CO_ * M_];                    // ospecT fp16 [b][o][m]

// ---------------- helpers ----------------
__device__ __forceinline__ uint32_t s2u(const void* p) {
    uint32_t a;
    asm("{ .reg .u64 t; cvta.to.shared.u64 t, %1; cvt.u32.u64 %0, t; }" : "=r"(a) : "l"(p));
    return a;
}
#define SW128(o) ((o) ^ (((o) >> 3) & 0x70))

#define LDSM4(d0, d1, d2, d3, addr)                                                  \
    asm volatile("ldmatrix.sync.aligned.m8n8.x4.shared.b16 {%0,%1,%2,%3}, [%4];"     \
                 : "=r"(d0), "=r"(d1), "=r"(d2), "=r"(d3) : "r"(addr))

#define MMA16816(d0, d1, d2, d3, a0, a1, a2, a3, b0, b1)                             \
    asm volatile("mma.sync.aligned.m16n8k16.row.col.f32.f16.f16.f32 "                \
                 "{%0,%1,%2,%3},{%4,%5,%6,%7},{%8,%9},{%0,%1,%2,%3};"                \
                 : "+f"(d0), "+f"(d1), "+f"(d2), "+f"(d3)                            \
                 : "r"(a0), "r"(a1), "r"(a2), "r"(a3), "r"(b0), "r"(b1))

#define CP_ASYNC16(saddr, gptr) \
    asm volatile("cp.async.cg.shared.global [%0], [%1], 16;" :: "r"(saddr), "l"(gptr))
#define CP_COMMIT() asm volatile("cp.async.commit_group;" ::: "memory")
#define CP_WAIT2()  asm volatile("cp.async.wait_group 2;" ::: "memory")

// packed f32x2 (for kMix)
__device__ __forceinline__ unsigned long long pk2(float lo, float hi) {
    unsigned long long r;
    asm("mov.b64 %0, {%1, %2};" : "=l"(r) : "f"(lo), "f"(hi));
    return r;
}
__device__ __forceinline__ unsigned long long ffma2(unsigned long long a,
                                                    unsigned long long b,
                                                    unsigned long long c) {
    unsigned long long d;
    asm("fma.rn.f32x2 %0, %1, %2, %3;" : "=l"(d) : "l"(a), "l"(b), "l"(c));
    return d;
}
__device__ __forceinline__ void upk2(unsigned long long v, float& lo, float& hi) {
    asm("mov.b64 {%0, %1}, %2;" : "=f"(lo), "=f"(hi) : "l"(v));
}

// ---------------- prep kernels ----------------
// U[n][m] fp32 -> U16[n][m] fp16 and Ut16[m][n] fp16
__global__ void kTransU(const float* __restrict__ U) {
    __shared__ float tile[32][33];
    int m0 = blockIdx.x * 32, n0 = blockIdx.y * 32;
    int tx = threadIdx.x, ty = threadIdx.y;  // 32 x 8
#pragma unroll
    for (int j = 0; j < 4; j++) {
        int nl = ty + j * 8;
        float v = U[(size_t)(n0 + nl) * M_ + m0 + tx];
        tile[nl][tx] = v;
        g_U16[(size_t)(n0 + nl) * M_ + m0 + tx] = __float2half(v);
    }
    __syncthreads();
#pragma unroll
    for (int j = 0; j < 4; j++) {
        int ml = ty + j * 8;
        g_Ut16[(size_t)(m0 + ml) * N_ + n0 + tx] = __float2half(tile[tx][ml]);
    }
}

// x[b][n][c] fp32 -> xT16[b][c][n] fp16
__global__ void kTransX(const float* __restrict__ x) {
    __shared__ float tile[32][33];
    int n0 = blockIdx.x * 32, c0 = blockIdx.y * 32, b = blockIdx.z;
    int tx = threadIdx.x, ty = threadIdx.y;
    const float* xb = x + (size_t)b * N_ * CI_;
#pragma unroll
    for (int j = 0; j < 4; j++)
        tile[ty + j * 8][tx] = xb[(size_t)(n0 + ty + j * 8) * CI_ + c0 + tx];
    __syncthreads();
    __half* oh = g_xT16 + (size_t)b * CI_ * N_;
#pragma unroll
    for (int j = 0; j < 4; j++) {
        int cl = ty + j * 8;
        oh[(size_t)(c0 + cl) * N_ + n0 + tx] = __float2half(tile[tx][cl]);
    }
}

__global__ void kTransW(const float* __restrict__ W) {
    __shared__ float tile[32][33];
    int m0 = blockIdx.x * 32, o0 = blockIdx.y * 32, c = blockIdx.z;
    int tx = threadIdx.x, ty = threadIdx.y;
    const float* Wc = W + (size_t)c * CO_ * M_;
#pragma unroll
    for (int j = 0; j < 4; j++)
        tile[ty + j * 8][tx] = Wc[(size_t)(o0 + ty + j * 8) * M_ + m0 + tx];
    __syncthreads();
#pragma unroll
    for (int j = 0; j < 4; j++)
        g_Wt[(size_t)(m0 + ty + j * 8) * CI_ * CO_ + (size_t)c * CO_ + o0 + tx] =
            tile[tx][ty + j * 8];
}

// ospec[b][m][o] fp32 -> oT16[b][o][m] fp16
__global__ void kTransO() {
    __shared__ float tile[32][33];
    int m0 = blockIdx.x * 32, o0 = blockIdx.y * 32, b = blockIdx.z;
    int tx = threadIdx.x, ty = threadIdx.y;
    const float* ob = g_ospec + (size_t)b * M_ * CO_;
#pragma unroll
    for (int j = 0; j < 4; j++)
        tile[ty + j * 8][tx] = ob[(size_t)(m0 + ty + j * 8) * CO_ + o0 + tx];
    __syncthreads();
    __half* oh = g_oT16 + (size_t)b * CO_ * M_;
#pragma unroll
    for (int j = 0; j < 4; j++) {
        int olc = ty + j * 8;
        oh[(size_t)(o0 + olc) * M_ + m0 + tx] = __float2half(tile[tx][olc]);
    }
}

// ---------------- single-pass fp16 TN GEMM, 128x256 tile (batch-paired) -------
// D[row][b-pair col] = sum_k A[row][k] * B[b][col][k]
// 512 threads = 16 warps (2 x 8), warp tile 64x32.
// Stage: A 16K | B 32K (two batches' 128-col tiles) = 48 KB; 4-stage ring.
#define STG_BYTES 49152
#define SM_TOTAL  (4 * STG_BYTES)

__device__ __forceinline__ void issueStage(
    uint32_t smb, int off, int tid,
    const __half* __restrict__ Ab, const __half* __restrict__ Bb,
    long strideB, int ldka, int ldkb, int kk)
{
#pragma unroll
    for (int i = 0; i < 2; i++) {   // A: 1024 16B-chunks (128 rows x 128B)
        int idx = tid + i * 512;
        int r = idx >> 3, ch = idx & 7;
        CP_ASYNC16(smb + off + SW128(r * 128 + ch * 16),
                   Ab + (size_t)r * ldka + kk + ch * 8);
    }
#pragma unroll
    for (int i = 0; i < 4; i++) {   // B: 2048 chunks (256 rows x 128B)
        int idx = tid + i * 512;
        int rb = idx >> 3, ch = idx & 7;
        const __half* src = Bb + ((rb >= 128) ? strideB : 0)
                            + (size_t)(rb & 127) * ldkb + kk + ch * 8;
        CP_ASYNC16(smb + off + 16384 + SW128(rb * 128 + ch * 16), src);
    }
}

__global__ void __launch_bounds__(512, 1) kGemmMMA(
    const __half* __restrict__ A16, int ldka,
    const __half* __restrict__ B16, int ldkb, long strideB,
    float* __restrict__ C, long strideC, long strideCz, int kseg0, int Ktot)
{
    extern __shared__ char sm[];
    const uint32_t smb = s2u(sm);
    const int tid = threadIdx.x, lane = tid & 31, wid = tid >> 5;
    const int wm = wid >> 3, wn = wid & 7;
    const int row0 = blockIdx.x * 128, bp = blockIdx.y, kz = blockIdx.z;
    const int kbase = kz * kseg0;
    const int Kseg = (kz == gridDim.z - 1) ? (Ktot - kbase) : kseg0;

    const __half* Ab = A16 + (size_t)row0 * ldka;
    const __half* Bb = B16 + (size_t)(2 * bp) * strideB;
    float* Cb0 = C + (size_t)kz * strideCz + (size_t)(2 * bp) * strideC
                 + (size_t)row0 * 128;

    const int S = Kseg / 64;

    float acc[4][4][4];
#pragma unroll
    for (int i = 0; i < 4; i++)
#pragma unroll
        for (int j = 0; j < 4; j++)
#pragma unroll
            for (int q = 0; q < 4; q++) acc[i][j][q] = 0.f;

    // prologue: stages 0..2
#pragma unroll
    for (int p = 0; p < 3; p++) {
        if (p < S) issueStage(smb, p * STG_BYTES, tid, Ab, Bb, strideB,
                              ldka, ldkb, kbase + p * 64);
        CP_COMMIT();
    }

    for (int s = 0; s < S; s++) {
        CP_WAIT2();           // stage s complete
        __syncthreads();
        if (s + 3 < S)
            issueStage(smb, ((s + 3) & 3) * STG_BYTES, tid, Ab, Bb, strideB,
                       ldka, ldkb, kbase + (s + 3) * 64);
        CP_COMMIT();

        const uint32_t stB = smb + (s & 3) * STG_BYTES;
        const uint32_t aBB = stB, bBB = stB + 16384;
#pragma unroll
        for (int ks = 0; ks < 4; ks++) {
            int kc16 = (ks * 2 + (lane >> 4)) * 16;
            uint32_t a[4][4], bfr[4][2];
            int rB = wn * 32 + (lane & 15);
#pragma unroll
            for (int nj = 0; nj < 2; nj++) {
                uint32_t r0, r1, r2, r3;
                LDSM4(r0, r1, r2, r3, bBB + SW128((rB + nj * 16) * 128 + kc16));
                bfr[nj * 2][0] = r0; bfr[nj * 2 + 1][0] = r1;
                bfr[nj * 2][1] = r2; bfr[nj * 2 + 1][1] = r3;
            }
            int rA = wm * 64 + (lane & 15);
#pragma unroll
            for (int mi = 0; mi < 4; mi++)
                LDSM4(a[mi][0], a[mi][1], a[mi][2], a[mi][3],
                      aBB + SW128((rA + mi * 16) * 128 + kc16));
#pragma unroll
            for (int mi = 0; mi < 4; mi++)
#pragma unroll
                for (int ni = 0; ni < 4; ni++)
                    MMA16816(acc[mi][ni][0], acc[mi][ni][1], acc[mi][ni][2], acc[mi][ni][3],
                             a[mi][0], a[mi][1], a[mi][2], a[mi][3],
                             bfr[ni][0], bfr[ni][1]);
        }
        __syncthreads();
    }

    // epilogue: warp's 32 cols live in one batch half (wn<4 -> b0, else b1)
    float* Cb = Cb0 + ((wn >= 4) ? strideC : 0);
    int g = lane >> 2, tg = lane & 3;
#pragma unroll
    for (int mi = 0; mi < 4; mi++)
#pragma unroll
        for (int ni = 0; ni < 4; ni++) {
            int r = wm * 64 + mi * 16 + g;
            int col = (wn * 32 + ni * 8 + tg * 2) & 127;
            *(float2*)&Cb[(size_t)r * 128 + col] =
                make_float2(acc[mi][ni][0], acc[mi][ni][1]);
            *(float2*)&Cb[(size_t)(r + 8) * 128 + col] =
                make_float2(acc[mi][ni][2], acc[mi][ni][3]);
        }
}

// ---------------- per-mode channel mixing (fp32 SIMT, sums KSPLIT partials) ---
__global__ void __launch_bounds__(256) kMix() {
    __shared__ float xs[32][128];
    __shared__ float ws[16][64];
    int m = blockIdx.x, h = blockIdx.y;
    int t = threadIdx.x;
    const size_t PS = (size_t)B_ * M_ * CI_;
#pragma unroll
    for (int i = 0; i < 4; i++) {
        int idx = i * 256 + t;
        int bb = idx >> 5;
        int cc = (idx & 31) << 2;
        const float* p = &g_xspecP[((size_t)bb * M_ + m) * CI_ + cc];
        float4 a = *(const float4*)p;
#pragma unroll
        for (int z = 1; z < KSPLIT; z++) {
            float4 v = *(const float4*)(p + (size_t)z * PS);
            a.x += v.x; a.y += v.y; a.z += v.z; a.w += v.w;
        }
        *(float4*)&xs[bb][cc] = a;
    }
    int tx = t & 15, ty = t >> 4;
    unsigned long long acc[2][2];
    acc[0][0] = acc[0][1] = acc[1][0] = acc[1][1] = 0ull;
    const float* Wm = g_Wt + (size_t)m * CI_ * CO_ + h * 64;
    for (int c0 = 0; c0 < CI_; c0 += 16) {
        __syncthreads();
        {
            int cr = t >> 4, oc = (t & 15) << 2;
            *(float4*)&ws[cr][oc] = *(const float4*)&Wm[(size_t)(c0 + cr) * CO_ + oc];
        }
        __syncthreads();
#pragma unroll
        for (int k = 0; k < 16; k++) {
            float4 b4 = *(const float4*)&ws[k][tx << 2];
            unsigned long long b01 = pk2(b4.x, b4.y);
            unsigned long long b23 = pk2(b4.z, b4.w);
#pragma unroll
            for (int i = 0; i < 2; i++) {
                float a = xs[ty * 2 + i][c0 + k];
                unsigned long long ad = pk2(a, a);
                acc[i][0] = ffma2(ad, b01, acc[i][0]);
                acc[i][1] = ffma2(ad, b23, acc[i][1]);
            }
        }
    }
#pragma unroll
    for (int i = 0; i < 2; i++) {
        float4 v;
        upk2(acc[i][0], v.x, v.y);
        upk2(acc[i][1], v.z, v.w);
        int bb = ty * 2 + i;
        *(float4*)&g_ospec[((size_t)bb * M_ + m) * CO_ + h * 64 + (tx << 2)] = v;
    }
}

// ---------------- launch ----------------
extern "C" void kernel_launch(void* const* d_in, const int* in_sizes, int n_in,
                              void* d_out, int out_size) {
    const float* x = (const float*)d_in[0];   // [B, N, C_in]
    const float* U = (const float*)d_in[1];   // [N, M]
    const float* W = (const float*)d_in[2];   // [C_in, C_out, M]
    float* out = (float*)d_out;               // [B, N, C_out]

    float* pXsP;
    __half *pUt, *pU, *pXT, *pOT;
    cudaGetSymbolAddress((void**)&pXsP, g_xspecP);
    cudaGetSymbolAddress((void**)&pUt, g_Ut16);
    cudaGetSymbolAddress((void**)&pU, g_U16);
    cudaGetSymbolAddress((void**)&pXT, g_xT16);
    cudaGetSymbolAddress((void**)&pOT, g_oT16);

    cudaFuncSetAttribute(kGemmMMA, cudaFuncAttributeMaxDynamicSharedMemorySize, SM_TOTAL);

    // prep
    kTransU<<<dim3(M_ / 32, N_ / 32), dim3(32, 8)>>>(U);
    kTransX<<<dim3(N_ / 32, CI_ / 32, B_), dim3(32, 8)>>>(x);
    kTransW<<<dim3(M_ / 32, CO_ / 32, CI_), dim3(32, 8)>>>(W);

    // GEMM1 (K-split x9): xspecP[kz][b][m][c] = sum_n Ut[m][n] * xT[b][c][n]
    kGemmMMA<<<dim3(M_ / 128, B_ / 2, KSPLIT), 512, SM_TOTAL>>>(
        pUt, N_,
        pXT, N_, (long)CI_ * N_,
        pXsP, (long)M_ * CI_, (long)B_ * M_ * CI_, KSEG0, N_);

    // mixing (sums the 9 partials) + transpose to fp16
    kMix<<<dim3(M_, 2), 256>>>();
    kTransO<<<dim3(M_ / 32, CO_ / 32, B_), dim3(32, 8)>>>();

    // GEMM2: out[b][n][o] = sum_m U[n][m] * oT[b][o][m]
    kGemmMMA<<<dim3(N_ / 128, B_ / 2, 1), 512, SM_TOTAL>>>(
        pU, M_,
        pOT, M_, (long)CO_ * M_,
        out, (long)N_ * CO_, 0, M_, M_);
}

// round 7
// speedup vs baseline: 4.4353x; 1.0471x over previous
#include <cuda_runtime.h>
#include <cuda_fp16.h>
#include <cstdint>

#define B_  32
#define N_  4096
#define CI_ 128
#define CO_ 128
#define M_  256
#define KSPLIT 9
#define KSEG0  448   // 7 x 64; last split gets 512 = 8 x 64

// ---------------- device scratch (no allocations allowed) ----------------
__device__ float g_xspecP[(size_t)KSPLIT * B_ * M_ * CI_];  // partial x_spec 36 MB
__device__ float g_ospec[B_ * M_ * CO_];                    // [b][m][o]
__device__ float g_Wt[M_ * CI_ * CO_];                      // [m][c][o]
__device__ __half g_Ut16[M_ * N_];                          // Ut fp16 [m][n]
__device__ __half g_U16[N_ * M_];                           // U  fp16 [n][m]
__device__ __half g_xT16[(size_t)B_ * CI_ * N_];            // xT fp16 [b][c][n]
__device__ __half g_oT16[B_ * CO_ * M_];                    // ospecT fp16 [b][o][m]

// ---------------- helpers ----------------
__device__ __forceinline__ uint32_t s2u(const void* p) {
    uint32_t a;
    asm("{ .reg .u64 t; cvta.to.shared.u64 t, %1; cvt.u32.u64 %0, t; }" : "=r"(a) : "l"(p));
    return a;
}
#define SW128(o) ((o) ^ (((o) >> 3) & 0x70))

#define LDSM4(d0, d1, d2, d3, addr)                                                  \
    asm volatile("ldmatrix.sync.aligned.m8n8.x4.shared.b16 {%0,%1,%2,%3}, [%4];"     \
                 : "=r"(d0), "=r"(d1), "=r"(d2), "=r"(d3) : "r"(addr))

#define MMA16816(d0, d1, d2, d3, a0, a1, a2, a3, b0, b1)                             \
    asm volatile("mma.sync.aligned.m16n8k16.row.col.f32.f16.f16.f32 "                \
                 "{%0,%1,%2,%3},{%4,%5,%6,%7},{%8,%9},{%0,%1,%2,%3};"                \
                 : "+f"(d0), "+f"(d1), "+f"(d2), "+f"(d3)                            \
                 : "r"(a0), "r"(a1), "r"(a2), "r"(a3), "r"(b0), "r"(b1))

#define CP_ASYNC16(saddr, gptr) \
    asm volatile("cp.async.cg.shared.global [%0], [%1], 16;" :: "r"(saddr), "l"(gptr))
#define CP_COMMIT() asm volatile("cp.async.commit_group;" ::: "memory")
#define CP_WAIT1()  asm volatile("cp.async.wait_group 1;" ::: "memory")

// packed f32x2 (for kMix)
__device__ __forceinline__ unsigned long long pk2(float lo, float hi) {
    unsigned long long r;
    asm("mov.b64 %0, {%1, %2};" : "=l"(r) : "f"(lo), "f"(hi));
    return r;
}
__device__ __forceinline__ unsigned long long ffma2(unsigned long long a,
                                                    unsigned long long b,
                                                    unsigned long long c) {
    unsigned long long d;
    asm("fma.rn.f32x2 %0, %1, %2, %3;" : "=l"(d) : "l"(a), "l"(b), "l"(c));
    return d;
}
__device__ __forceinline__ void upk2(unsigned long long v, float& lo, float& hi) {
    asm("mov.b64 {%0, %1}, %2;" : "=f"(lo), "=f"(hi) : "l"(v));
}

// ---------------- prep kernels ----------------
// U[n][m] fp32 -> U16[n][m] fp16 and Ut16[m][n] fp16
__global__ void kTransU(const float* __restrict__ U) {
    __shared__ float tile[32][33];
    int m0 = blockIdx.x * 32, n0 = blockIdx.y * 32;
    int tx = threadIdx.x, ty = threadIdx.y;  // 32 x 8
#pragma unroll
    for (int j = 0; j < 4; j++) {
        int nl = ty + j * 8;
        float v = U[(size_t)(n0 + nl) * M_ + m0 + tx];
        tile[nl][tx] = v;
        g_U16[(size_t)(n0 + nl) * M_ + m0 + tx] = __float2half(v);
    }
    __syncthreads();
#pragma unroll
    for (int j = 0; j < 4; j++) {
        int ml = ty + j * 8;
        g_Ut16[(size_t)(m0 + ml) * N_ + n0 + tx] = __float2half(tile[tx][ml]);
    }
}

// x[b][n][c] fp32 -> xT16[b][c][n] fp16
__global__ void kTransX(const float* __restrict__ x) {
    __shared__ float tile[32][33];
    int n0 = blockIdx.x * 32, c0 = blockIdx.y * 32, b = blockIdx.z;
    int tx = threadIdx.x, ty = threadIdx.y;
    const float* xb = x + (size_t)b * N_ * CI_;
#pragma unroll
    for (int j = 0; j < 4; j++)
        tile[ty + j * 8][tx] = xb[(size_t)(n0 + ty + j * 8) * CI_ + c0 + tx];
    __syncthreads();
    __half* oh = g_xT16 + (size_t)b * CI_ * N_;
#pragma unroll
    for (int j = 0; j < 4; j++) {
        int cl = ty + j * 8;
        oh[(size_t)(c0 + cl) * N_ + n0 + tx] = __float2half(tile[tx][cl]);
    }
}

__global__ void kTransW(const float* __restrict__ W) {
    __shared__ float tile[32][33];
    int m0 = blockIdx.x * 32, o0 = blockIdx.y * 32, c = blockIdx.z;
    int tx = threadIdx.x, ty = threadIdx.y;
    const float* Wc = W + (size_t)c * CO_ * M_;
#pragma unroll
    for (int j = 0; j < 4; j++)
        tile[ty + j * 8][tx] = Wc[(size_t)(o0 + ty + j * 8) * M_ + m0 + tx];
    __syncthreads();
#pragma unroll
    for (int j = 0; j < 4; j++)
        g_Wt[(size_t)(m0 + ty + j * 8) * CI_ * CO_ + (size_t)c * CO_ + o0 + tx] =
            tile[tx][ty + j * 8];
}

// ospec[b][m][o] fp32 -> oT16[b][o][m] fp16
__global__ void kTransO() {
    __shared__ float tile[32][33];
    int m0 = blockIdx.x * 32, o0 = blockIdx.y * 32, b = blockIdx.z;
    int tx = threadIdx.x, ty = threadIdx.y;
    const float* ob = g_ospec + (size_t)b * M_ * CO_;
#pragma unroll
    for (int j = 0; j < 4; j++)
        tile[ty + j * 8][tx] = ob[(size_t)(m0 + ty + j * 8) * CO_ + o0 + tx];
    __syncthreads();
    __half* oh = g_oT16 + (size_t)b * CO_ * M_;
#pragma unroll
    for (int j = 0; j < 4; j++) {
        int olc = ty + j * 8;
        oh[(size_t)(o0 + olc) * M_ + m0 + tx] = __float2half(tile[tx][olc]);
    }
}

// ---------------- single-pass fp16 TN GEMM, 128x128 tile, 2 CTAs/SM ----------
// D[row][col] = sum_k A[row][k] * B[b][col][k]
// 256 threads = 8 warps (2 x 4), warp tile 64x32.
// Stage: A 16K | B 16K = 32 KB; 3-stage ring (96 KB) -> 2 CTAs/SM.
#define STG_BYTES 32768
#define SM_TOTAL  (3 * STG_BYTES)

__device__ __forceinline__ void issueStage(
    uint32_t smb, int off, int tid,
    const __half* __restrict__ Ab, const __half* __restrict__ Bb,
    int ldka, int ldkb, int kk)
{
#pragma unroll
    for (int i = 0; i < 4; i++) {   // A: 1024 16B-chunks (128 rows x 128B)
        int idx = tid + i * 256;
        int r = idx >> 3, ch = idx & 7;
        CP_ASYNC16(smb + off + SW128(r * 128 + ch * 16),
                   Ab + (size_t)r * ldka + kk + ch * 8);
    }
#pragma unroll
    for (int i = 0; i < 4; i++) {   // B: 1024 chunks (128 rows x 128B)
        int idx = tid + i * 256;
        int r = idx >> 3, ch = idx & 7;
        CP_ASYNC16(smb + off + 16384 + SW128(r * 128 + ch * 16),
                   Bb + (size_t)r * ldkb + kk + ch * 8);
    }
}

__global__ void __launch_bounds__(256, 2) kGemmMMA(
    const __half* __restrict__ A16, int ldka,
    const __half* __restrict__ B16, int ldkb, long strideB,
    float* __restrict__ C, long strideC, long strideCz, int kseg0, int Ktot)
{
    extern __shared__ char sm[];
    const uint32_t smb = s2u(sm);
    const int tid = threadIdx.x, lane = tid & 31, wid = tid >> 5;
    const int wm = wid >> 2, wn = wid & 3;
    const int row0 = blockIdx.x * 128, b = blockIdx.y, kz = blockIdx.z;
    const int kbase = kz * kseg0;
    const int Kseg = (kz == gridDim.z - 1) ? (Ktot - kbase) : kseg0;

    const __half* Ab = A16 + (size_t)row0 * ldka;
    const __half* Bb = B16 + (size_t)b * strideB;
    float* Cb = C + (size_t)kz * strideCz + (size_t)b * strideC
                + (size_t)row0 * 128;

    const int S = Kseg / 64;

    float acc[4][4][4];
#pragma unroll
    for (int i = 0; i < 4; i++)
#pragma unroll
        for (int j = 0; j < 4; j++)
#pragma unroll
            for (int q = 0; q < 4; q++) acc[i][j][q] = 0.f;

    // prologue: stages 0,1
    issueStage(smb, 0, tid, Ab, Bb, ldka, ldkb, kbase);
    CP_COMMIT();
    if (S > 1) issueStage(smb, STG_BYTES, tid, Ab, Bb, ldka, ldkb, kbase + 64);
    CP_COMMIT();

    for (int s = 0; s < S; s++) {
        CP_WAIT1();           // stage s landed (this thread's groups)
        __syncthreads();      // all threads' stage-s data visible
        if (s + 2 < S)
            issueStage(smb, ((s + 2) % 3) * STG_BYTES, tid, Ab, Bb,
                       ldka, ldkb, kbase + (s + 2) * 64);
        CP_COMMIT();

        const uint32_t stB = smb + (s % 3) * STG_BYTES;
        const uint32_t aBB = stB, bBB = stB + 16384;
#pragma unroll
        for (int ks = 0; ks < 4; ks++) {
            int kc16 = (ks * 2 + (lane >> 4)) * 16;
            uint32_t a[4][4], bfr[4][2];
            int rB = wn * 32 + (lane & 15);
#pragma unroll
            for (int nj = 0; nj < 2; nj++) {
                uint32_t r0, r1, r2, r3;
                LDSM4(r0, r1, r2, r3, bBB + SW128((rB + nj * 16) * 128 + kc16));
                bfr[nj * 2][0] = r0; bfr[nj * 2 + 1][0] = r1;
                bfr[nj * 2][1] = r2; bfr[nj * 2 + 1][1] = r3;
            }
            int rA = wm * 64 + (lane & 15);
#pragma unroll
            for (int mi = 0; mi < 4; mi++)
                LDSM4(a[mi][0], a[mi][1], a[mi][2], a[mi][3],
                      aBB + SW128((rA + mi * 16) * 128 + kc16));
#pragma unroll
            for (int mi = 0; mi < 4; mi++)
#pragma unroll
                for (int ni = 0; ni < 4; ni++)
                    MMA16816(acc[mi][ni][0], acc[mi][ni][1], acc[mi][ni][2], acc[mi][ni][3],
                             a[mi][0], a[mi][1], a[mi][2], a[mi][3],
                             bfr[ni][0], bfr[ni][1]);
        }
        // no tail barrier: single top-of-loop sync bounds warp skew to <1 stage,
        // and the next write (s+2) targets a buffer last read at s-1, which all
        // warps finished before passing the top sync of stage s.
    }

    // epilogue
    int g = lane >> 2, tg = lane & 3;
#pragma unroll
    for (int mi = 0; mi < 4; mi++)
#pragma unroll
        for (int ni = 0; ni < 4; ni++) {
            int r = wm * 64 + mi * 16 + g;
            int col = wn * 32 + ni * 8 + tg * 2;
            *(float2*)&Cb[(size_t)r * 128 + col] =
                make_float2(acc[mi][ni][0], acc[mi][ni][1]);
            *(float2*)&Cb[(size_t)(r + 8) * 128 + col] =
                make_float2(acc[mi][ni][2], acc[mi][ni][3]);
        }
}

// ---------------- per-mode channel mixing (fp32 SIMT, sums KSPLIT partials) ---
__global__ void __launch_bounds__(256) kMix() {
    __shared__ float xs[32][128];
    __shared__ float ws[16][64];
    int m = blockIdx.x, h = blockIdx.y;
    int t = threadIdx.x;
    const size_t PS = (size_t)B_ * M_ * CI_;
#pragma unroll
    for (int i = 0; i < 4; i++) {
        int idx = i * 256 + t;
        int bb = idx >> 5;
        int cc = (idx & 31) << 2;
        const float* p = &g_xspecP[((size_t)bb * M_ + m) * CI_ + cc];
        float4 a = *(const float4*)p;
#pragma unroll
        for (int z = 1; z < KSPLIT; z++) {
            float4 v = *(const float4*)(p + (size_t)z * PS);
            a.x += v.x; a.y += v.y; a.z += v.z; a.w += v.w;
        }
        *(float4*)&xs[bb][cc] = a;
    }
    int tx = t & 15, ty = t >> 4;
    unsigned long long acc[2][2];
    acc[0][0] = acc[0][1] = acc[1][0] = acc[1][1] = 0ull;
    const float* Wm = g_Wt + (size_t)m * CI_ * CO_ + h * 64;
    for (int c0 = 0; c0 < CI_; c0 += 16) {
        __syncthreads();
        {
            int cr = t >> 4, oc = (t & 15) << 2;
            *(float4*)&ws[cr][oc] = *(const float4*)&Wm[(size_t)(c0 + cr) * CO_ + oc];
        }
        __syncthreads();
#pragma unroll
        for (int k = 0; k < 16; k++) {
            float4 b4 = *(const float4*)&ws[k][tx << 2];
            unsigned long long b01 = pk2(b4.x, b4.y);
            unsigned long long b23 = pk2(b4.z, b4.w);
#pragma unroll
            for (int i = 0; i < 2; i++) {
                float a = xs[ty * 2 + i][c0 + k];
                unsigned long long ad = pk2(a, a);
                acc[i][0] = ffma2(ad, b01, acc[i][0]);
                acc[i][1] = ffma2(ad, b23, acc[i][1]);
            }
        }
    }
#pragma unroll
    for (int i = 0; i < 2; i++) {
        float4 v;
        upk2(acc[i][0], v.x, v.y);
        upk2(acc[i][1], v.z, v.w);
        int bb = ty * 2 + i;
        *(float4*)&g_ospec[((size_t)bb * M_ + m) * CO_ + h * 64 + (tx << 2)] = v;
    }
}

// ---------------- launch ----------------
extern "C" void kernel_launch(void* const* d_in, const int* in_sizes, int n_in,
                              void* d_out, int out_size) {
    const float* x = (const float*)d_in[0];   // [B, N, C_in]
    const float* U = (const float*)d_in[1];   // [N, M]
    const float* W = (const float*)d_in[2];   // [C_in, C_out, M]
    float* out = (float*)d_out;               // [B, N, C_out]

    float* pXsP;
    __half *pUt, *pU, *pXT, *pOT;
    cudaGetSymbolAddress((void**)&pXsP, g_xspecP);
    cudaGetSymbolAddress((void**)&pUt, g_Ut16);
    cudaGetSymbolAddress((void**)&pU, g_U16);
    cudaGetSymbolAddress((void**)&pXT, g_xT16);
    cudaGetSymbolAddress((void**)&pOT, g_oT16);

    cudaFuncSetAttribute(kGemmMMA, cudaFuncAttributeMaxDynamicSharedMemorySize, SM_TOTAL);

    // prep
    kTransU<<<dim3(M_ / 32, N_ / 32), dim3(32, 8)>>>(U);
    kTransX<<<dim3(N_ / 32, CI_ / 32, B_), dim3(32, 8)>>>(x);
    kTransW<<<dim3(M_ / 32, CO_ / 32, CI_), dim3(32, 8)>>>(W);

    // GEMM1 (K-split x9): xspecP[kz][b][m][c] = sum_n Ut[m][n] * xT[b][c][n]
    kGemmMMA<<<dim3(M_ / 128, B_, KSPLIT), 256, SM_TOTAL>>>(
        pUt, N_,
        pXT, N_, (long)CI_ * N_,
        pXsP, (long)M_ * CI_, (long)B_ * M_ * CI_, KSEG0, N_);

    // mixing (sums the 9 partials) + transpose to fp16
    kMix<<<dim3(M_, 2), 256>>>();
    kTransO<<<dim3(M_ / 32, CO_ / 32, B_), dim3(32, 8)>>>();

    // GEMM2: out[b][n][o] = sum_m U[n][m] * oT[b][o][m]
    kGemmMMA<<<dim3(N_ / 128, B_, 1), 256, SM_TOTAL>>>(
        pU, M_,
        pOT, M_, (long)CO_ * M_,
        out, (long)N_ * CO_, 0, M_, M_);
}

// round 8
// speedup vs baseline: 4.5836x; 1.0334x over previous
#include <cuda_runtime.h>
#include <cuda_fp16.h>
#include <cstdint>

#define B_  32
#define N_  4096
#define CI_ 128
#define CO_ 128
#define M_  256
#define KSPLIT 9
#define KSEG0  448   // 7 x 64; last split gets 512 = 8 x 64

// ---------------- device scratch (no allocations allowed) ----------------
__device__ float g_xspecP[(size_t)KSPLIT * B_ * M_ * CI_];  // partial x_spec 36 MB
__device__ float g_ospec[B_ * M_ * CO_];                    // [b][m][o]
__device__ float g_Wt[M_ * CI_ * CO_];                      // [m][c][o]
__device__ __half g_Ut16[M_ * N_];                          // Ut fp16 [m][n]
__device__ __half g_U16[N_ * M_];                           // U  fp16 [n][m]
__device__ __half g_xT16[(size_t)B_ * CI_ * N_];            // xT fp16 [b][c][n]
__device__ __half g_oT16[B_ * CO_ * M_];                    // ospecT fp16 [b][o][m]

// ---------------- helpers ----------------
__device__ __forceinline__ uint32_t s2u(const void* p) {
    uint32_t a;
    asm("{ .reg .u64 t; cvta.to.shared.u64 t, %1; cvt.u32.u64 %0, t; }" : "=r"(a) : "l"(p));
    return a;
}
#define SW128(o) ((o) ^ (((o) >> 3) & 0x70))

#define LDSM4(d0, d1, d2, d3, addr)                                                  \
    asm volatile("ldmatrix.sync.aligned.m8n8.x4.shared.b16 {%0,%1,%2,%3}, [%4];"     \
                 : "=r"(d0), "=r"(d1), "=r"(d2), "=r"(d3) : "r"(addr))

#define MMA16816(d0, d1, d2, d3, a0, a1, a2, a3, b0, b1)                             \
    asm volatile("mma.sync.aligned.m16n8k16.row.col.f32.f16.f16.f32 "                \
                 "{%0,%1,%2,%3},{%4,%5,%6,%7},{%8,%9},{%0,%1,%2,%3};"                \
                 : "+f"(d0), "+f"(d1), "+f"(d2), "+f"(d3)                            \
                 : "r"(a0), "r"(a1), "r"(a2), "r"(a3), "r"(b0), "r"(b1))

#define CP_ASYNC16(saddr, gptr) \
    asm volatile("cp.async.cg.shared.global [%0], [%1], 16;" :: "r"(saddr), "l"(gptr))
#define CP_COMMIT() asm volatile("cp.async.commit_group;" ::: "memory")
#define CP_WAIT1()  asm volatile("cp.async.wait_group 1;" ::: "memory")

// load a warp's 4 B n-block fragments for k16-chunk ks into dst[4][2]
#define LOADB(dst, bBB, ks) do {                                                     \
    int _kc = ((ks) * 2 + (lane >> 4)) * 16;                                         \
    int _rB = wn * 32 + (lane & 15);                                                 \
    uint32_t _r0, _r1, _r2, _r3;                                                     \
    LDSM4(_r0, _r1, _r2, _r3, (bBB) + SW128(_rB * 128 + _kc));                       \
    dst[0][0] = _r0; dst[1][0] = _r1; dst[0][1] = _r2; dst[1][1] = _r3;              \
    LDSM4(_r0, _r1, _r2, _r3, (bBB) + SW128((_rB + 16) * 128 + _kc));                \
    dst[2][0] = _r0; dst[3][0] = _r1; dst[2][1] = _r2; dst[3][1] = _r3;              \
} while (0)

// packed f32x2 (for kMix)
__device__ __forceinline__ unsigned long long pk2(float lo, float hi) {
    unsigned long long r;
    asm("mov.b64 %0, {%1, %2};" : "=l"(r) : "f"(lo), "f"(hi));
    return r;
}
__device__ __forceinline__ unsigned long long ffma2(unsigned long long a,
                                                    unsigned long long b,
                                                    unsigned long long c) {
    unsigned long long d;
    asm("fma.rn.f32x2 %0, %1, %2, %3;" : "=l"(d) : "l"(a), "l"(b), "l"(c));
    return d;
}
__device__ __forceinline__ void upk2(unsigned long long v, float& lo, float& hi) {
    asm("mov.b64 {%0, %1}, %2;" : "=f"(lo), "=f"(hi) : "l"(v));
}

// ---------------- fused prep kernel ----------------
// blocks [0,1024): U transpose/cast; [1024,17408): x transpose/cast;
// [17408,21504): W transpose. All 32x8 threads.
#define PREP_U 1024
#define PREP_X (1024 + 16384)
#define PREP_TOTAL (PREP_X + 4096)

__global__ void kPrep(const float* __restrict__ x, const float* __restrict__ U,
                      const float* __restrict__ W) {
    __shared__ float tile[32][33];
    int tx = threadIdx.x, ty = threadIdx.y;
    int bid = blockIdx.x;
    if (bid < PREP_U) {
        int m0 = (bid & 7) * 32, n0 = (bid >> 3) * 32;
#pragma unroll
        for (int j = 0; j < 4; j++) {
            int nl = ty + j * 8;
            float v = U[(size_t)(n0 + nl) * M_ + m0 + tx];
            tile[nl][tx] = v;
            g_U16[(size_t)(n0 + nl) * M_ + m0 + tx] = __float2half(v);
        }
        __syncthreads();
#pragma unroll
        for (int j = 0; j < 4; j++) {
            int ml = ty + j * 8;
            g_Ut16[(size_t)(m0 + ml) * N_ + n0 + tx] = __float2half(tile[tx][ml]);
        }
    } else if (bid < PREP_X) {
        int t = bid - PREP_U;
        int n0 = (t & 127) * 32, c0 = ((t >> 7) & 3) * 32, b = t >> 9;
        const float* xb = x + (size_t)b * N_ * CI_;
#pragma unroll
        for (int j = 0; j < 4; j++)
            tile[ty + j * 8][tx] = xb[(size_t)(n0 + ty + j * 8) * CI_ + c0 + tx];
        __syncthreads();
        __half* oh = g_xT16 + (size_t)b * CI_ * N_;
#pragma unroll
        for (int j = 0; j < 4; j++) {
            int cl = ty + j * 8;
            oh[(size_t)(c0 + cl) * N_ + n0 + tx] = __float2half(tile[tx][cl]);
        }
    } else {
        int t = bid - PREP_X;
        int m0 = (t & 7) * 32, o0 = ((t >> 3) & 3) * 32, c = t >> 5;
        const float* Wc = W + (size_t)c * CO_ * M_;
#pragma unroll
        for (int j = 0; j < 4; j++)
            tile[ty + j * 8][tx] = Wc[(size_t)(o0 + ty + j * 8) * M_ + m0 + tx];
        __syncthreads();
#pragma unroll
        for (int j = 0; j < 4; j++)
            g_Wt[(size_t)(m0 + ty + j * 8) * CI_ * CO_ + (size_t)c * CO_ + o0 + tx] =
                tile[tx][ty + j * 8];
    }
}

// ospec[b][m][o] fp32 -> oT16[b][o][m] fp16
__global__ void kTransO() {
    __shared__ float tile[32][33];
    int m0 = blockIdx.x * 32, o0 = blockIdx.y * 32, b = blockIdx.z;
    int tx = threadIdx.x, ty = threadIdx.y;
    const float* ob = g_ospec + (size_t)b * M_ * CO_;
#pragma unroll
    for (int j = 0; j < 4; j++)
        tile[ty + j * 8][tx] = ob[(size_t)(m0 + ty + j * 8) * CO_ + o0 + tx];
    __syncthreads();
    __half* oh = g_oT16 + (size_t)b * CO_ * M_;
#pragma unroll
    for (int j = 0; j < 4; j++) {
        int olc = ty + j * 8;
        oh[(size_t)(o0 + olc) * M_ + m0 + tx] = __float2half(tile[tx][olc]);
    }
}

// ---------------- single-pass fp16 TN GEMM, 128x128 tile, 2 CTAs/SM ----------
// D[row][col] = sum_k A[row][k] * B[b][col][k]
// 256 threads = 8 warps (2 x 4), warp tile 64x32.
// Stage: A 16K | B 16K = 32 KB; 3-stage ring (96 KB).
// Inner loop explicitly software-pipelined: B frags double-buffered across
// k16 chunks, A frags double-buffered across mi.
#define STG_BYTES 32768
#define SM_TOTAL  (3 * STG_BYTES)

__device__ __forceinline__ void issueStage(
    uint32_t smb, int off, int tid,
    const __half* __restrict__ Ab, const __half* __restrict__ Bb,
    int ldka, int ldkb, int kk)
{
#pragma unroll
    for (int i = 0; i < 4; i++) {   // A: 1024 16B-chunks (128 rows x 128B)
        int idx = tid + i * 256;
        int r = idx >> 3, ch = idx & 7;
        CP_ASYNC16(smb + off + SW128(r * 128 + ch * 16),
                   Ab + (size_t)r * ldka + kk + ch * 8);
    }
#pragma unroll
    for (int i = 0; i < 4; i++) {   // B: 1024 chunks
        int idx = tid + i * 256;
        int r = idx >> 3, ch = idx & 7;
        CP_ASYNC16(smb + off + 16384 + SW128(r * 128 + ch * 16),
                   Bb + (size_t)r * ldkb + kk + ch * 8);
    }
}

__global__ void __launch_bounds__(256, 2) kGemmMMA(
    const __half* __restrict__ A16, int ldka,
    const __half* __restrict__ B16, int ldkb, long strideB,
    float* __restrict__ C, long strideC, long strideCz, int kseg0, int Ktot)
{
    extern __shared__ char sm[];
    const uint32_t smb = s2u(sm);
    const int tid = threadIdx.x, lane = tid & 31, wid = tid >> 5;
    const int wm = wid >> 2, wn = wid & 3;
    const int row0 = blockIdx.x * 128, b = blockIdx.y, kz = blockIdx.z;
    const int kbase = kz * kseg0;
    const int Kseg = (kz == gridDim.z - 1) ? (Ktot - kbase) : kseg0;

    const __half* Ab = A16 + (size_t)row0 * ldka;
    const __half* Bb = B16 + (size_t)b * strideB;
    float* Cb = C + (size_t)kz * strideCz + (size_t)b * strideC
                + (size_t)row0 * 128;

    const int S = Kseg / 64;

    float acc[4][4][4];
#pragma unroll
    for (int i = 0; i < 4; i++)
#pragma unroll
        for (int j = 0; j < 4; j++)
#pragma unroll
            for (int q = 0; q < 4; q++) acc[i][j][q] = 0.f;

    // prologue: stages 0,1
    issueStage(smb, 0, tid, Ab, Bb, ldka, ldkb, kbase);
    CP_COMMIT();
    if (S > 1) issueStage(smb, STG_BYTES, tid, Ab, Bb, ldka, ldkb, kbase + 64);
    CP_COMMIT();

    const int rA = wm * 64 + (lane & 15);

    for (int s = 0; s < S; s++) {
        CP_WAIT1();           // stage s landed
        __syncthreads();      // all threads' stage-s data visible
        if (s + 2 < S)
            issueStage(smb, ((s + 2) % 3) * STG_BYTES, tid, Ab, Bb,
                       ldka, ldkb, kbase + (s + 2) * 64);
        CP_COMMIT();

        const uint32_t stB = smb + (s % 3) * STG_BYTES;
        const uint32_t aBB = stB, bBB = stB + 16384;

        uint32_t bfr[2][4][2];
        uint32_t av[2][4];
        LOADB(bfr[0], bBB, 0);
#pragma unroll
        for (int ks = 0; ks < 4; ks++) {
            const int kc16 = (ks * 2 + (lane >> 4)) * 16;
            // prefetch next chunk's B fragments
            if (ks < 3) LOADB(bfr[(ks + 1) & 1], bBB, ks + 1);
            // A[0] for this chunk
            LDSM4(av[0][0], av[0][1], av[0][2], av[0][3],
                  aBB + SW128(rA * 128 + kc16));
#pragma unroll
            for (int mi = 0; mi < 4; mi++) {
                if (mi < 3)   // prefetch A[mi+1] before consuming A[mi]
                    LDSM4(av[(mi + 1) & 1][0], av[(mi + 1) & 1][1],
                          av[(mi + 1) & 1][2], av[(mi + 1) & 1][3],
                          aBB + SW128((rA + (mi + 1) * 16) * 128 + kc16));
                uint32_t* a = av[mi & 1];
#pragma unroll
                for (int ni = 0; ni < 4; ni++)
                    MMA16816(acc[mi][ni][0], acc[mi][ni][1], acc[mi][ni][2], acc[mi][ni][3],
                             a[0], a[1], a[2], a[3],
                             bfr[ks & 1][ni][0], bfr[ks & 1][ni][1]);
            }
        }
        // single top-of-loop sync per stage; 3-stage ring keeps reuse safe
    }

    // epilogue
    int g = lane >> 2, tg = lane & 3;
#pragma unroll
    for (int mi = 0; mi < 4; mi++)
#pragma unroll
        for (int ni = 0; ni < 4; ni++) {
            int r = wm * 64 + mi * 16 + g;
            int col = wn * 32 + ni * 8 + tg * 2;
            *(float2*)&Cb[(size_t)r * 128 + col] =
                make_float2(acc[mi][ni][0], acc[mi][ni][1]);
            *(float2*)&Cb[(size_t)(r + 8) * 128 + col] =
                make_float2(acc[mi][ni][2], acc[mi][ni][3]);
        }
}

// ---------------- per-mode channel mixing (fp32 SIMT, sums KSPLIT partials) ---
__global__ void __launch_bounds__(256) kMix() {
    __shared__ float xs[32][128];
    __shared__ float ws[16][64];
    int m = blockIdx.x, h = blockIdx.y;
    int t = threadIdx.x;
    const size_t PS = (size_t)B_ * M_ * CI_;
#pragma unroll
    for (int i = 0; i < 4; i++) {
        int idx = i * 256 + t;
        int bb = idx >> 5;
        int cc = (idx & 31) << 2;
        const float* p = &g_xspecP[((size_t)bb * M_ + m) * CI_ + cc];
        float4 a = *(const float4*)p;
#pragma unroll
        for (int z = 1; z < KSPLIT; z++) {
            float4 v = *(const float4*)(p + (size_t)z * PS);
            a.x += v.x; a.y += v.y; a.z += v.z; a.w += v.w;
        }
        *(float4*)&xs[bb][cc] = a;
    }
    int tx = t & 15, ty = t >> 4;
    unsigned long long acc[2][2];
    acc[0][0] = acc[0][1] = acc[1][0] = acc[1][1] = 0ull;
    const float* Wm = g_Wt + (size_t)m * CI_ * CO_ + h * 64;
    for (int c0 = 0; c0 < CI_; c0 += 16) {
        __syncthreads();
        {
            int cr = t >> 4, oc = (t & 15) << 2;
            *(float4*)&ws[cr][oc] = *(const float4*)&Wm[(size_t)(c0 + cr) * CO_ + oc];
        }
        __syncthreads();
#pragma unroll
        for (int k = 0; k < 16; k++) {
            float4 b4 = *(const float4*)&ws[k][tx << 2];
            unsigned long long b01 = pk2(b4.x, b4.y);
            unsigned long long b23 = pk2(b4.z, b4.w);
#pragma unroll
            for (int i = 0; i < 2; i++) {
                float a = xs[ty * 2 + i][c0 + k];
                unsigned long long ad = pk2(a, a);
                acc[i][0] = ffma2(ad, b01, acc[i][0]);
                acc[i][1] = ffma2(ad, b23, acc[i][1]);
            }
        }
    }
#pragma unroll
    for (int i = 0; i < 2; i++) {
        float4 v;
        upk2(acc[i][0], v.x, v.y);
        upk2(acc[i][1], v.z, v.w);
        int bb = ty * 2 + i;
        *(float4*)&g_ospec[((size_t)bb * M_ + m) * CO_ + h * 64 + (tx << 2)] = v;
    }
}

// ---------------- launch ----------------
extern "C" void kernel_launch(void* const* d_in, const int* in_sizes, int n_in,
                              void* d_out, int out_size) {
    const float* x = (const float*)d_in[0];   // [B, N, C_in]
    const float* U = (const float*)d_in[1];   // [N, M]
    const float* W = (const float*)d_in[2];   // [C_in, C_out, M]
    float* out = (float*)d_out;               // [B, N, C_out]

    float* pXsP;
    __half *pUt, *pU, *pXT, *pOT;
    cudaGetSymbolAddress((void**)&pXsP, g_xspecP);
    cudaGetSymbolAddress((void**)&pUt, g_Ut16);
    cudaGetSymbolAddress((void**)&pU, g_U16);
    cudaGetSymbolAddress((void**)&pXT, g_xT16);
    cudaGetSymbolAddress((void**)&pOT, g_oT16);

    cudaFuncSetAttribute(kGemmMMA, cudaFuncAttributeMaxDynamicSharedMemorySize, SM_TOTAL);

    // fused prep
    kPrep<<<PREP_TOTAL, dim3(32, 8)>>>(x, U, W);

    // GEMM1 (K-split x9): xspecP[kz][b][m][c] = sum_n Ut[m][n] * xT[b][c][n]
    kGemmMMA<<<dim3(M_ / 128, B_, KSPLIT), 256, SM_TOTAL>>>(
        pUt, N_,
        pXT, N_, (long)CI_ * N_,
        pXsP, (long)M_ * CI_, (long)B_ * M_ * CI_, KSEG0, N_);

    // mixing (sums the 9 partials) + transpose to fp16
    kMix<<<dim3(M_, 2), 256>>>();
    kTransO<<<dim3(M_ / 32, CO_ / 32, B_), dim3(32, 8)>>>();

    // GEMM2: out[b][n][o] = sum_m U[n][m] * oT[b][o][m]
    kGemmMMA<<<dim3(N_ / 128, B_, 1), 256, SM_TOTAL>>>(
        pU, M_,
        pOT, M_, (long)CO_ * M_,
        out, (long)N_ * CO_, 0, M_, M_);
}

// round 9
// speedup vs baseline: 4.8023x; 1.0477x over previous
#include <cuda_runtime.h>
#include <cuda_fp16.h>
#include <cstdint>

#define B_  32
#define N_  4096
#define CI_ 128
#define CO_ 128
#define M_  256
#define KSPLIT 9
#define KSEG0  448   // 7 x 64; last split gets 512 = 8 x 64

// ---------------- device scratch (no allocations allowed) ----------------
__device__ float g_xspec[B_ * M_ * CI_];                    // accumulated x_spec 4 MB
__device__ float g_ospec[B_ * M_ * CO_];                    // [b][m][o]
__device__ float g_Wt[M_ * CI_ * CO_];                      // [m][c][o]
__device__ __half g_Ut16[M_ * N_];                          // Ut fp16 [m][n]
__device__ __half g_U16[N_ * M_];                           // U  fp16 [n][m]
__device__ __half g_xT16[(size_t)B_ * CI_ * N_];            // xT fp16 [b][c][n]
__device__ __half g_oT16[B_ * CO_ * M_];                    // ospecT fp16 [b][o][m]

// ---------------- helpers ----------------
__device__ __forceinline__ uint32_t s2u(const void* p) {
    uint32_t a;
    asm("{ .reg .u64 t; cvta.to.shared.u64 t, %1; cvt.u32.u64 %0, t; }" : "=r"(a) : "l"(p));
    return a;
}
#define SW128(o) ((o) ^ (((o) >> 3) & 0x70))

#define LDSM4(d0, d1, d2, d3, addr)                                                  \
    asm volatile("ldmatrix.sync.aligned.m8n8.x4.shared.b16 {%0,%1,%2,%3}, [%4];"     \
                 : "=r"(d0), "=r"(d1), "=r"(d2), "=r"(d3) : "r"(addr))

#define MMA16816(d0, d1, d2, d3, a0, a1, a2, a3, b0, b1)                             \
    asm volatile("mma.sync.aligned.m16n8k16.row.col.f32.f16.f16.f32 "                \
                 "{%0,%1,%2,%3},{%4,%5,%6,%7},{%8,%9},{%0,%1,%2,%3};"                \
                 : "+f"(d0), "+f"(d1), "+f"(d2), "+f"(d3)                            \
                 : "r"(a0), "r"(a1), "r"(a2), "r"(a3), "r"(b0), "r"(b1))

#define CP_ASYNC16(saddr, gptr) \
    asm volatile("cp.async.cg.shared.global [%0], [%1], 16;" :: "r"(saddr), "l"(gptr))
#define CP_COMMIT() asm volatile("cp.async.commit_group;" ::: "memory")
#define CP_WAIT1()  asm volatile("cp.async.wait_group 1;" ::: "memory")

#define REDGF(ptr, val) \
    asm volatile("red.global.add.f32 [%0], %1;" :: "l"(ptr), "f"(val) : "memory")

// load a warp's 4 B n-block fragments for k16-chunk ks into dst[4][2]
#define LOADB(dst, bBB, ks) do {                                                     \
    int _kc = ((ks) * 2 + (lane >> 4)) * 16;                                         \
    int _rB = wn * 32 + (lane & 15);                                                 \
    uint32_t _r0, _r1, _r2, _r3;                                                     \
    LDSM4(_r0, _r1, _r2, _r3, (bBB) + SW128(_rB * 128 + _kc));                       \
    dst[0][0] = _r0; dst[1][0] = _r1; dst[0][1] = _r2; dst[1][1] = _r3;              \
    LDSM4(_r0, _r1, _r2, _r3, (bBB) + SW128((_rB + 16) * 128 + _kc));                \
    dst[2][0] = _r0; dst[3][0] = _r1; dst[2][1] = _r2; dst[3][1] = _r3;              \
} while (0)

// packed f32x2 (for kMix)
__device__ __forceinline__ unsigned long long pk2(float lo, float hi) {
    unsigned long long r;
    asm("mov.b64 %0, {%1, %2};" : "=l"(r) : "f"(lo), "f"(hi));
    return r;
}
__device__ __forceinline__ unsigned long long ffma2(unsigned long long a,
                                                    unsigned long long b,
                                                    unsigned long long c) {
    unsigned long long d;
    asm("fma.rn.f32x2 %0, %1, %2, %3;" : "=l"(d) : "l"(a), "l"(b), "l"(c));
    return d;
}
__device__ __forceinline__ void upk2(unsigned long long v, float& lo, float& hi) {
    asm("mov.b64 {%0, %1}, %2;" : "=f"(lo), "=f"(hi) : "l"(v));
}

// ---------------- fused prep kernel ----------------
// blocks [0,1024): U transpose/cast (32x32 tiles)
// [1024, 1024+8192): x transpose/cast (64n x 32c tiles, half2 stores)
// next 4096: W transpose
// last 256: zero g_xspec
#define PREP_U 1024
#define PREP_X (PREP_U + 8192)
#define PREP_W (PREP_X + 4096)
#define PREP_TOTAL (PREP_W + 256)

__global__ void kPrep(const float* __restrict__ x, const float* __restrict__ U,
                      const float* __restrict__ W) {
    int tx = threadIdx.x, ty = threadIdx.y;  // 32 x 8
    int bid = blockIdx.x;
    if (bid < PREP_U) {
        __shared__ float tile[32][33];
        int m0 = (bid & 7) * 32, n0 = (bid >> 3) * 32;
#pragma unroll
        for (int j = 0; j < 4; j++) {
            int nl = ty + j * 8;
            float v = U[(size_t)(n0 + nl) * M_ + m0 + tx];
            tile[nl][tx] = v;
            g_U16[(size_t)(n0 + nl) * M_ + m0 + tx] = __float2half(v);
        }
        __syncthreads();
#pragma unroll
        for (int j = 0; j < 4; j++) {
            int ml = ty + j * 8;
            g_Ut16[(size_t)(m0 + ml) * N_ + n0 + tx] = __float2half(tile[tx][ml]);
        }
    } else if (bid < PREP_X) {
        // x[b][n][c] fp32 -> xT16[b][c][n] fp16, 64n x 32c tile
        __shared__ float ts[64][33];
        int t = bid - PREP_U;
        int n0 = (t & 63) * 64, c0 = ((t >> 6) & 3) * 32, b = t >> 8;
        const float* xb = x + (size_t)b * N_ * CI_;
#pragma unroll
        for (int j = 0; j < 8; j++) {
            int nl = ty + j * 8;
            ts[nl][tx] = xb[(size_t)(n0 + nl) * CI_ + c0 + tx];
        }
        __syncthreads();
        __half* oh = g_xT16 + (size_t)b * CI_ * N_;
#pragma unroll
        for (int j = 0; j < 4; j++) {
            int cl = ty + j * 8;
            __half2 v = __floats2half2_rn(ts[2 * tx][cl], ts[2 * tx + 1][cl]);
            *(__half2*)(oh + (size_t)(c0 + cl) * N_ + n0 + 2 * tx) = v;
        }
    } else if (bid < PREP_W) {
        __shared__ float tile[32][33];
        int t = bid - PREP_X;
        int m0 = (t & 7) * 32, o0 = ((t >> 3) & 3) * 32, c = t >> 5;
        const float* Wc = W + (size_t)c * CO_ * M_;
#pragma unroll
        for (int j = 0; j < 4; j++)
            tile[ty + j * 8][tx] = Wc[(size_t)(o0 + ty + j * 8) * M_ + m0 + tx];
        __syncthreads();
#pragma unroll
        for (int j = 0; j < 4; j++)
            g_Wt[(size_t)(m0 + ty + j * 8) * CI_ * CO_ + (size_t)c * CO_ + o0 + tx] =
                tile[tx][ty + j * 8];
    } else {
        // zero g_xspec: 256 blocks x 16 KB
        int t = bid - PREP_W;
        float4* p = (float4*)g_xspec + (size_t)t * 1024;
        int tid = ty * 32 + tx;
#pragma unroll
        for (int i = 0; i < 4; i++)
            p[tid + i * 256] = make_float4(0.f, 0.f, 0.f, 0.f);
    }
}

// ospec[b][m][o] fp32 -> oT16[b][o][m] fp16; 64m x 32o tiles, half2 stores
__global__ void kTransO() {
    __shared__ float ts[32][65];
    int m0 = blockIdx.x * 64, o0 = blockIdx.y * 32, b = blockIdx.z;
    int tx = threadIdx.x, ty = threadIdx.y;  // 32 x 8
    const float* ob = g_ospec + (size_t)b * M_ * CO_;
#pragma unroll
    for (int j = 0; j < 8; j++) {
        int ml = ty + j * 8;
        ts[tx][ml] = ob[(size_t)(m0 + ml) * CO_ + o0 + tx];
    }
    __syncthreads();
    __half* oh = g_oT16 + (size_t)b * CO_ * M_;
#pragma unroll
    for (int j = 0; j < 4; j++) {
        int ol = ty + j * 8;
        __half2 v = __floats2half2_rn(ts[ol][2 * tx], ts[ol][2 * tx + 1]);
        *(__half2*)(oh + (size_t)(o0 + ol) * M_ + m0 + 2 * tx) = v;
    }
}

// ---------------- single-pass fp16 TN GEMM, 128x128 tile, 2 CTAs/SM ----------
#define STG_BYTES 32768
#define SM_TOTAL  (3 * STG_BYTES)

__device__ __forceinline__ void issueStage(
    uint32_t smb, int off, int tid,
    const __half* __restrict__ Ab, const __half* __restrict__ Bb,
    int ldka, int ldkb, int kk)
{
#pragma unroll
    for (int i = 0; i < 4; i++) {
        int idx = tid + i * 256;
        int r = idx >> 3, ch = idx & 7;
        CP_ASYNC16(smb + off + SW128(r * 128 + ch * 16),
                   Ab + (size_t)r * ldka + kk + ch * 8);
    }
#pragma unroll
    for (int i = 0; i < 4; i++) {
        int idx = tid + i * 256;
        int r = idx >> 3, ch = idx & 7;
        CP_ASYNC16(smb + off + 16384 + SW128(r * 128 + ch * 16),
                   Bb + (size_t)r * ldkb + kk + ch * 8);
    }
}

__global__ void __launch_bounds__(256, 2) kGemmMMA(
    const __half* __restrict__ A16, int ldka,
    const __half* __restrict__ B16, int ldkb, long strideB,
    float* __restrict__ C, long strideC, int kseg0, int Ktot, int accum)
{
    extern __shared__ char sm[];
    const uint32_t smb = s2u(sm);
    const int tid = threadIdx.x, lane = tid & 31, wid = tid >> 5;
    const int wm = wid >> 2, wn = wid & 3;
    const int row0 = blockIdx.x * 128, b = blockIdx.y, kz = blockIdx.z;
    const int kbase = kz * kseg0;
    const int Kseg = (kz == gridDim.z - 1) ? (Ktot - kbase) : kseg0;

    const __half* Ab = A16 + (size_t)row0 * ldka;
    const __half* Bb = B16 + (size_t)b * strideB;
    float* Cb = C + (size_t)b * strideC + (size_t)row0 * 128;

    const int S = Kseg / 64;

    float acc[4][4][4];
#pragma unroll
    for (int i = 0; i < 4; i++)
#pragma unroll
        for (int j = 0; j < 4; j++)
#pragma unroll
            for (int q = 0; q < 4; q++) acc[i][j][q] = 0.f;

    issueStage(smb, 0, tid, Ab, Bb, ldka, ldkb, kbase);
    CP_COMMIT();
    if (S > 1) issueStage(smb, STG_BYTES, tid, Ab, Bb, ldka, ldkb, kbase + 64);
    CP_COMMIT();

    const int rA = wm * 64 + (lane & 15);

    for (int s = 0; s < S; s++) {
        CP_WAIT1();
        __syncthreads();
        if (s + 2 < S)
            issueStage(smb, ((s + 2) % 3) * STG_BYTES, tid, Ab, Bb,
                       ldka, ldkb, kbase + (s + 2) * 64);
        CP_COMMIT();

        const uint32_t stB = smb + (s % 3) * STG_BYTES;
        const uint32_t aBB = stB, bBB = stB + 16384;

        uint32_t bfr[2][4][2];
        uint32_t av[2][4];
        LOADB(bfr[0], bBB, 0);
#pragma unroll
        for (int ks = 0; ks < 4; ks++) {
            const int kc16 = (ks * 2 + (lane >> 4)) * 16;
            if (ks < 3) LOADB(bfr[(ks + 1) & 1], bBB, ks + 1);
            LDSM4(av[0][0], av[0][1], av[0][2], av[0][3],
                  aBB + SW128(rA * 128 + kc16));
#pragma unroll
            for (int mi = 0; mi < 4; mi++) {
                if (mi < 3)
                    LDSM4(av[(mi + 1) & 1][0], av[(mi + 1) & 1][1],
                          av[(mi + 1) & 1][2], av[(mi + 1) & 1][3],
                          aBB + SW128((rA + (mi + 1) * 16) * 128 + kc16));
                uint32_t* a = av[mi & 1];
#pragma unroll
                for (int ni = 0; ni < 4; ni++)
                    MMA16816(acc[mi][ni][0], acc[mi][ni][1], acc[mi][ni][2], acc[mi][ni][3],
                             a[0], a[1], a[2], a[3],
                             bfr[ks & 1][ni][0], bfr[ks & 1][ni][1]);
            }
        }
    }

    // epilogue
    int g = lane >> 2, tg = lane & 3;
    if (accum) {
#pragma unroll
        for (int mi = 0; mi < 4; mi++)
#pragma unroll
            for (int ni = 0; ni < 4; ni++) {
                int r = wm * 64 + mi * 16 + g;
                int col = wn * 32 + ni * 8 + tg * 2;
                float* p0 = &Cb[(size_t)r * 128 + col];
                float* p1 = &Cb[(size_t)(r + 8) * 128 + col];
                REDGF(p0, acc[mi][ni][0]);
                REDGF(p0 + 1, acc[mi][ni][1]);
                REDGF(p1, acc[mi][ni][2]);
                REDGF(p1 + 1, acc[mi][ni][3]);
            }
    } else {
#pragma unroll
        for (int mi = 0; mi < 4; mi++)
#pragma unroll
            for (int ni = 0; ni < 4; ni++) {
                int r = wm * 64 + mi * 16 + g;
                int col = wn * 32 + ni * 8 + tg * 2;
                *(float2*)&Cb[(size_t)r * 128 + col] =
                    make_float2(acc[mi][ni][0], acc[mi][ni][1]);
                *(float2*)&Cb[(size_t)(r + 8) * 128 + col] =
                    make_float2(acc[mi][ni][2], acc[mi][ni][3]);
            }
    }
}

// ---------------- per-mode channel mixing (fp32 SIMT) ----------------
__global__ void __launch_bounds__(256) kMix() {
    __shared__ float xs[32][128];
    __shared__ float ws[16][64];
    int m = blockIdx.x, h = blockIdx.y;
    int t = threadIdx.x;
#pragma unroll
    for (int i = 0; i < 4; i++) {
        int idx = i * 256 + t;
        int bb = idx >> 5;
        int cc = (idx & 31) << 2;
        *(float4*)&xs[bb][cc] =
            *(const float4*)&g_xspec[((size_t)bb * M_ + m) * CI_ + cc];
    }
    int tx = t & 15, ty = t >> 4;
    unsigned long long acc[2][2];
    acc[0][0] = acc[0][1] = acc[1][0] = acc[1][1] = 0ull;
    const float* Wm = g_Wt + (size_t)m * CI_ * CO_ + h * 64;
    for (int c0 = 0; c0 < CI_; c0 += 16) {
        __syncthreads();
        {
            int cr = t >> 4, oc = (t & 15) << 2;
            *(float4*)&ws[cr][oc] = *(const float4*)&Wm[(size_t)(c0 + cr) * CO_ + oc];
        }
        __syncthreads();
#pragma unroll
        for (int k = 0; k < 16; k++) {
            float4 b4 = *(const float4*)&ws[k][tx << 2];
            unsigned long long b01 = pk2(b4.x, b4.y);
            unsigned long long b23 = pk2(b4.z, b4.w);
#pragma unroll
            for (int i = 0; i < 2; i++) {
                float a = xs[ty * 2 + i][c0 + k];
                unsigned long long ad = pk2(a, a);
                acc[i][0] = ffma2(ad, b01, acc[i][0]);
                acc[i][1] = ffma2(ad, b23, acc[i][1]);
            }
        }
    }
#pragma unroll
    for (int i = 0; i < 2; i++) {
        float4 v;
        upk2(acc[i][0], v.x, v.y);
        upk2(acc[i][1], v.z, v.w);
        int bb = ty * 2 + i;
        *(float4*)&g_ospec[((size_t)bb * M_ + m) * CO_ + h * 64 + (tx << 2)] = v;
    }
}

// ---------------- launch ----------------
extern "C" void kernel_launch(void* const* d_in, const int* in_sizes, int n_in,
                              void* d_out, int out_size) {
    const float* x = (const float*)d_in[0];   // [B, N, C_in]
    const float* U = (const float*)d_in[1];   // [N, M]
    const float* W = (const float*)d_in[2];   // [C_in, C_out, M]
    float* out = (float*)d_out;               // [B, N, C_out]

    float* pXs;
    __half *pUt, *pU, *pXT, *pOT;
    cudaGetSymbolAddress((void**)&pXs, g_xspec);
    cudaGetSymbolAddress((void**)&pUt, g_Ut16);
    cudaGetSymbolAddress((void**)&pU, g_U16);
    cudaGetSymbolAddress((void**)&pXT, g_xT16);
    cudaGetSymbolAddress((void**)&pOT, g_oT16);

    cudaFuncSetAttribute(kGemmMMA, cudaFuncAttributeMaxDynamicSharedMemorySize, SM_TOTAL);

    // fused prep (also zeroes g_xspec for the REDG accumulation)
    kPrep<<<PREP_TOTAL, dim3(32, 8)>>>(x, U, W);

    // GEMM1 (K-split x9, REDG accumulate): xspec[b][m][c] += Ut[m][n]*xT[b][c][n]
    kGemmMMA<<<dim3(M_ / 128, B_, KSPLIT), 256, SM_TOTAL>>>(
        pUt, N_,
        pXT, N_, (long)CI_ * N_,
        pXs, (long)M_ * CI_, KSEG0, N_, 1);

    // mixing + transpose to fp16
    kMix<<<dim3(M_, 2), 256>>>();
    kTransO<<<dim3(M_ / 64, CO_ / 32, B_), dim3(32, 8)>>>();

    // GEMM2: out[b][n][o] = sum_m U[n][m] * oT[b][o][m]
    kGemmMMA<<<dim3(N_ / 128, B_, 1), 256, SM_TOTAL>>>(
        pU, M_,
        pOT, M_, (long)CO_ * M_,
        out, (long)N_ * CO_, M_, M_, 0);
}

// round 10
// speedup vs baseline: 5.0196x; 1.0453x over previous
#include <cuda_runtime.h>
#include <cuda_fp16.h>
#include <cstdint>

#define B_  32
#define N_  4096
#define CI_ 128
#define CO_ 128
#define M_  256
#define KSPLIT 9
#define KSEG0  448   // 7 x 64; last split gets 512 = 8 x 64

// ---------------- device scratch (no allocations allowed) ----------------
__device__ float g_xspec[B_ * M_ * CI_];                    // accumulated x_spec 4 MB
__device__ float g_Wt[M_ * CI_ * CO_];                      // [m][c][o] 16 MB
__device__ __half g_U16[N_ * M_];                           // U fp16 [n][m] 2 MB
__device__ __half g_x16[(size_t)B_ * N_ * CI_];             // x fp16 [b][n][c] 32 MB
__device__ __half g_oM16[B_ * M_ * CO_];                    // mixed spec fp16 [b][m][o] 2 MB

// ---------------- helpers ----------------
__device__ __forceinline__ uint32_t s2u(const void* p) {
    uint32_t a;
    asm("{ .reg .u64 t; cvta.to.shared.u64 t, %1; cvt.u32.u64 %0, t; }" : "=r"(a) : "l"(p));
    return a;
}
#define SW128(o) ((o) ^ (((o) >> 3) & 0x70))

#define LDSM4(d0, d1, d2, d3, addr)                                                  \
    asm volatile("ldmatrix.sync.aligned.m8n8.x4.shared.b16 {%0,%1,%2,%3}, [%4];"     \
                 : "=r"(d0), "=r"(d1), "=r"(d2), "=r"(d3) : "r"(addr))

#define LDSM4T(d0, d1, d2, d3, addr)                                                 \
    asm volatile("ldmatrix.sync.aligned.m8n8.x4.trans.shared.b16 {%0,%1,%2,%3}, [%4];" \
                 : "=r"(d0), "=r"(d1), "=r"(d2), "=r"(d3) : "r"(addr))

#define MMA16816(d0, d1, d2, d3, a0, a1, a2, a3, b0, b1)                             \
    asm volatile("mma.sync.aligned.m16n8k16.row.col.f32.f16.f16.f32 "                \
                 "{%0,%1,%2,%3},{%4,%5,%6,%7},{%8,%9},{%0,%1,%2,%3};"                \
                 : "+f"(d0), "+f"(d1), "+f"(d2), "+f"(d3)                            \
                 : "r"(a0), "r"(a1), "r"(a2), "r"(a3), "r"(b0), "r"(b1))

#define CP_ASYNC16(saddr, gptr) \
    asm volatile("cp.async.cg.shared.global [%0], [%1], 16;" :: "r"(saddr), "l"(gptr))
#define CP_COMMIT() asm volatile("cp.async.commit_group;" ::: "memory")
#define CP_WAIT1()  asm volatile("cp.async.wait_group 1;" ::: "memory")

#define REDGF(ptr, val) \
    asm volatile("red.global.add.f32 [%0], %1;" :: "l"(ptr), "f"(val) : "memory")

// trans-fragment address inside a [64k x 128col] fp16 tile with seg^k swizzle.
// per-thread constants: kboff = (8*(lane>=16) + lane&7)*256, cadd = (lane>>3)&1, l7.
#define TADDR(tile, ks, col0) \
    ((tile) + (ks) * 4096 + kboff + (((((col0) >> 3) + cadd) ^ l7) << 4))

// load 4 n-block B fragments (32 cols) of chunk ks from a trans tile
#define LOADB_T(dst, bTile, ks) do {                                                 \
    uint32_t _r0, _r1, _r2, _r3;                                                     \
    LDSM4T(_r0, _r1, _r2, _r3, TADDR(bTile, ks, wn * 32));                           \
    dst[0][0] = _r0; dst[1][0] = _r1; dst[0][1] = _r2; dst[1][1] = _r3;              \
    LDSM4T(_r0, _r1, _r2, _r3, TADDR(bTile, ks, wn * 32 + 16));                      \
    dst[2][0] = _r0; dst[3][0] = _r1; dst[2][1] = _r2; dst[3][1] = _r3;              \
} while (0)

// packed f32x2 (for kMix)
__device__ __forceinline__ unsigned long long pk2(float lo, float hi) {
    unsigned long long r;
    asm("mov.b64 %0, {%1, %2};" : "=l"(r) : "f"(lo), "f"(hi));
    return r;
}
__device__ __forceinline__ unsigned long long ffma2(unsigned long long a,
                                                    unsigned long long b,
                                                    unsigned long long c) {
    unsigned long long d;
    asm("fma.rn.f32x2 %0, %1, %2, %3;" : "=l"(d) : "l"(a), "l"(b), "l"(c));
    return d;
}
__device__ __forceinline__ void upk2(unsigned long long v, float& lo, float& hi) {
    asm("mov.b64 {%0, %1}, %2;" : "=f"(lo), "=f"(hi) : "l"(v));
}

// ---------------- fused prep kernel (pure casts + W transpose + zero) --------
#define PB_X 4096                  // x cast: 4,194,304 float4 chunks
#define PB_U (PB_X + 256)          // U cast: 262,144 chunks
#define PB_W (PB_U + 4096)         // W transpose
#define PREP_TOTAL (PB_W + 256)    // zero g_xspec

__global__ void __launch_bounds__(256) kPrep(const float* __restrict__ x,
                                             const float* __restrict__ U,
                                             const float* __restrict__ W) {
    int tid = threadIdx.x;
    int bid = blockIdx.x;
    if (bid < PB_X) {
        const float4* src = (const float4*)x;
        size_t base = (size_t)bid * 1024 + tid;
#pragma unroll
        for (int i = 0; i < 4; i++) {
            size_t c = base + i * 256;
            float4 v = src[c];
            union { __half2 h[2]; uint2 u; } cv;
            cv.h[0] = __floats2half2_rn(v.x, v.y);
            cv.h[1] = __floats2half2_rn(v.z, v.w);
            ((uint2*)g_x16)[c] = cv.u;
        }
    } else if (bid < PB_U) {
        const float4* src = (const float4*)U;
        size_t base = (size_t)(bid - PB_X) * 1024 + tid;
#pragma unroll
        for (int i = 0; i < 4; i++) {
            size_t c = base + i * 256;
            float4 v = src[c];
            union { __half2 h[2]; uint2 u; } cv;
            cv.h[0] = __floats2half2_rn(v.x, v.y);
            cv.h[1] = __floats2half2_rn(v.z, v.w);
            ((uint2*)g_U16)[c] = cv.u;
        }
    } else if (bid < PB_W) {
        __shared__ float tile[32][33];
        int t = bid - PB_U;
        int tx = tid & 31, ty = tid >> 5;
        int m0 = (t & 7) * 32, o0 = ((t >> 3) & 3) * 32, c = t >> 5;
        const float* Wc = W + (size_t)c * CO_ * M_;
#pragma unroll
        for (int j = 0; j < 4; j++)
            tile[ty + j * 8][tx] = Wc[(size_t)(o0 + ty + j * 8) * M_ + m0 + tx];
        __syncthreads();
#pragma unroll
        for (int j = 0; j < 4; j++)
            g_Wt[(size_t)(m0 + ty + j * 8) * CI_ * CO_ + (size_t)c * CO_ + o0 + tx] =
                tile[tx][ty + j * 8];
    } else {
        int t = bid - PB_W;
        float4* p = (float4*)g_xspec + (size_t)t * 1024;
#pragma unroll
        for (int i = 0; i < 4; i++)
            p[tid + i * 256] = make_float4(0.f, 0.f, 0.f, 0.f);
    }
}

// ---------------- fp16 TN GEMM, 128x128 tile, 2 CTAs/SM ----------------------
// ATRANS=1: A consumed via trans-ldmatrix from [k][m] source (U16 [n][m]).
// B always consumed via trans-ldmatrix from [k][col] source.
// Stage: A 16K | B 16K = 32 KB; 3-stage ring (96 KB).
#define STG_BYTES 32768
#define SM_TOTAL  (3 * STG_BYTES)

template <int ATRANS>
__global__ void __launch_bounds__(256, 2) kGemm(
    const __half* __restrict__ A16, long aStride,
    const __half* __restrict__ B16, long bStride, long strideB,
    float* __restrict__ C, long strideC, int kseg0, int Ktot, int accum)
{
    extern __shared__ char sm[];
    const uint32_t smb = s2u(sm);
    const int tid = threadIdx.x, lane = tid & 31, wid = tid >> 5;
    const int wm = wid >> 2, wn = wid & 3;
    const int row0 = blockIdx.x * 128, b = blockIdx.y, kz = blockIdx.z;
    const int kbase = kz * kseg0;
    const int Kseg = (kz == gridDim.z - 1) ? (Ktot - kbase) : kseg0;

    const __half* Bb = B16 + (size_t)b * strideB;
    float* Cb = C + (size_t)b * strideC + (size_t)row0 * 128;

    const int S = Kseg / 64;

    // per-thread trans-fragment constants
    const int l7 = lane & 7;
    const int cadd = (lane >> 3) & 1;
    const uint32_t kboff = (uint32_t)((((lane & 16) >> 1) + l7) * 256);

    float acc[4][4][4];
#pragma unroll
    for (int i = 0; i < 4; i++)
#pragma unroll
        for (int j = 0; j < 4; j++)
#pragma unroll
            for (int q = 0; q < 4; q++) acc[i][j][q] = 0.f;

    // stage issue (lambda captures)
    auto issue = [&](int off, int kk) {
        if (ATRANS) {
#pragma unroll
            for (int i = 0; i < 4; i++) {  // A trans tile: 64 rows x 16 segs
                int idx = tid + i * 256;
                int k = idx >> 4, seg = idx & 15;
                CP_ASYNC16(smb + off + k * 256 + (((seg ^ (k & 7))) << 4),
                           A16 + (size_t)(kk + k) * aStride + row0 + seg * 8);
            }
        } else {
#pragma unroll
            for (int i = 0; i < 4; i++) {  // A plain tile: 128 rows x 8 chunks
                int idx = tid + i * 256;
                int r = idx >> 3, ch = idx & 7;
                CP_ASYNC16(smb + off + SW128(r * 128 + ch * 16),
                           A16 + (size_t)(row0 + r) * aStride + kk + ch * 8);
            }
        }
#pragma unroll
        for (int i = 0; i < 4; i++) {      // B trans tile: 64 rows x 16 segs
            int idx = tid + i * 256;
            int k = idx >> 4, seg = idx & 15;
            CP_ASYNC16(smb + off + 16384 + k * 256 + (((seg ^ (k & 7))) << 4),
                       Bb + (size_t)(kk + k) * bStride + seg * 8);
        }
    };

    issue(0, kbase);
    CP_COMMIT();
    if (S > 1) issue(STG_BYTES, kbase + 64);
    CP_COMMIT();

    const int rA = wm * 64 + (lane & 15);  // plain-A row index

    for (int s = 0; s < S; s++) {
        CP_WAIT1();
        __syncthreads();
        if (s + 2 < S) issue(((s + 2) % 3) * STG_BYTES, kbase + (s + 2) * 64);
        CP_COMMIT();

        const uint32_t stB = smb + (s % 3) * STG_BYTES;
        const uint32_t aT = stB, bT = stB + 16384;

        uint32_t bfr[2][4][2];
        uint32_t av[2][4];
        LOADB_T(bfr[0], bT, 0);
#pragma unroll
        for (int ks = 0; ks < 4; ks++) {
            if (ks < 3) LOADB_T(bfr[(ks + 1) & 1], bT, ks + 1);
            if (ATRANS) {
                LDSM4T(av[0][0], av[0][1], av[0][2], av[0][3],
                       TADDR(aT, ks, wm * 64));
            } else {
                const int kc16 = (ks * 2 + (lane >> 4)) * 16;
                LDSM4(av[0][0], av[0][1], av[0][2], av[0][3],
                      aT + SW128(rA * 128 + kc16));
            }
#pragma unroll
            for (int mi = 0; mi < 4; mi++) {
                if (mi < 3) {
                    if (ATRANS) {
                        LDSM4T(av[(mi + 1) & 1][0], av[(mi + 1) & 1][1],
                               av[(mi + 1) & 1][2], av[(mi + 1) & 1][3],
                               TADDR(aT, ks, wm * 64 + (mi + 1) * 16));
                    } else {
                        const int kc16 = (ks * 2 + (lane >> 4)) * 16;
                        LDSM4(av[(mi + 1) & 1][0], av[(mi + 1) & 1][1],
                              av[(mi + 1) & 1][2], av[(mi + 1) & 1][3],
                              aT + SW128((rA + (mi + 1) * 16) * 128 + kc16));
                    }
                }
                uint32_t* a = av[mi & 1];
#pragma unroll
                for (int ni = 0; ni < 4; ni++)
                    MMA16816(acc[mi][ni][0], acc[mi][ni][1], acc[mi][ni][2], acc[mi][ni][3],
                             a[0], a[1], a[2], a[3],
                             bfr[ks & 1][ni][0], bfr[ks & 1][ni][1]);
            }
        }
    }

    // epilogue
    int g = lane >> 2, tg = lane & 3;
    if (accum) {
#pragma unroll
        for (int mi = 0; mi < 4; mi++)
#pragma unroll
            for (int ni = 0; ni < 4; ni++) {
                int r = wm * 64 + mi * 16 + g;
                int col = wn * 32 + ni * 8 + tg * 2;
                float* p0 = &Cb[(size_t)r * 128 + col];
                float* p1 = &Cb[(size_t)(r + 8) * 128 + col];
                REDGF(p0, acc[mi][ni][0]);
                REDGF(p0 + 1, acc[mi][ni][1]);
                REDGF(p1, acc[mi][ni][2]);
                REDGF(p1 + 1, acc[mi][ni][3]);
            }
    } else {
#pragma unroll
        for (int mi = 0; mi < 4; mi++)
#pragma unroll
            for (int ni = 0; ni < 4; ni++) {
                int r = wm * 64 + mi * 16 + g;
                int col = wn * 32 + ni * 8 + tg * 2;
                *(float2*)&Cb[(size_t)r * 128 + col] =
                    make_float2(acc[mi][ni][0], acc[mi][ni][1]);
                *(float2*)&Cb[(size_t)(r + 8) * 128 + col] =
                    make_float2(acc[mi][ni][2], acc[mi][ni][3]);
            }
    }
}

// ---------------- per-mode channel mixing (fp32 SIMT -> fp16 out) -------------
__global__ void __launch_bounds__(256) kMix() {
    __shared__ float xs[32][128];
    __shared__ float ws[16][64];
    int m = blockIdx.x, hh = blockIdx.y;
    int t = threadIdx.x;
#pragma unroll
    for (int i = 0; i < 4; i++) {
        int idx = i * 256 + t;
        int bb = idx >> 5;
        int cc = (idx & 31) << 2;
        *(float4*)&xs[bb][cc] =
            *(const float4*)&g_xspec[((size_t)bb * M_ + m) * CI_ + cc];
    }
    int tx = t & 15, ty = t >> 4;
    unsigned long long acc[2][2];
    acc[0][0] = acc[0][1] = acc[1][0] = acc[1][1] = 0ull;
    const float* Wm = g_Wt + (size_t)m * CI_ * CO_ + hh * 64;
    for (int c0 = 0; c0 < CI_; c0 += 16) {
        __syncthreads();
        {
            int cr = t >> 4, oc = (t & 15) << 2;
            *(float4*)&ws[cr][oc] = *(const float4*)&Wm[(size_t)(c0 + cr) * CO_ + oc];
        }
        __syncthreads();
#pragma unroll
        for (int k = 0; k < 16; k++) {
            float4 b4 = *(const float4*)&ws[k][tx << 2];
            unsigned long long b01 = pk2(b4.x, b4.y);
            unsigned long long b23 = pk2(b4.z, b4.w);
#pragma unroll
            for (int i = 0; i < 2; i++) {
                float a = xs[ty * 2 + i][c0 + k];
                unsigned long long ad = pk2(a, a);
                acc[i][0] = ffma2(ad, b01, acc[i][0]);
                acc[i][1] = ffma2(ad, b23, acc[i][1]);
            }
        }
    }
#pragma unroll
    for (int i = 0; i < 2; i++) {
        float4 v;
        upk2(acc[i][0], v.x, v.y);
        upk2(acc[i][1], v.z, v.w);
        int bb = ty * 2 + i;
        union { __half2 h[2]; uint2 u; } cv;
        cv.h[0] = __floats2half2_rn(v.x, v.y);
        cv.h[1] = __floats2half2_rn(v.z, v.w);
        *(uint2*)(g_oM16 + ((size_t)bb * M_ + m) * CO_ + hh * 64 + (tx << 2)) = cv.u;
    }
}

// ---------------- launch ----------------
extern "C" void kernel_launch(void* const* d_in, const int* in_sizes, int n_in,
                              void* d_out, int out_size) {
    const float* x = (const float*)d_in[0];   // [B, N, C_in]
    const float* U = (const float*)d_in[1];   // [N, M]
    const float* W = (const float*)d_in[2];   // [C_in, C_out, M]
    float* out = (float*)d_out;               // [B, N, C_out]

    float* pXs;
    __half *pU, *pX, *pO;
    cudaGetSymbolAddress((void**)&pXs, g_xspec);
    cudaGetSymbolAddress((void**)&pU, g_U16);
    cudaGetSymbolAddress((void**)&pX, g_x16);
    cudaGetSymbolAddress((void**)&pO, g_oM16);

    cudaFuncSetAttribute(kGemm<1>, cudaFuncAttributeMaxDynamicSharedMemorySize, SM_TOTAL);
    cudaFuncSetAttribute(kGemm<0>, cudaFuncAttributeMaxDynamicSharedMemorySize, SM_TOTAL);

    // fused prep: casts + W transpose + zero g_xspec
    kPrep<<<PREP_TOTAL, 256>>>(x, U, W);

    // GEMM1 (A-trans from U16, B-trans from x16, REDG accumulate):
    // xspec[b][m][c] += sum_n U[n][m] * x[b][n][c]
    kGemm<1><<<dim3(M_ / 128, B_, KSPLIT), 256, SM_TOTAL>>>(
        pU, M_,
        pX, CI_, (long)N_ * CI_,
        pXs, (long)M_ * CI_, KSEG0, N_, 1);

    // mixing (writes fp16 oM16 directly)
    kMix<<<dim3(M_, 2), 256>>>();

    // GEMM2 (A-plain from U16, B-trans from oM16):
    // out[b][n][o] = sum_m U[n][m] * oM[b][m][o]
    kGemm<0><<<dim3(N_ / 128, B_, 1), 256, SM_TOTAL>>>(
        pU, M_,
        pO, CO_, (long)M_ * CO_,
        out, (long)N_ * CO_, M_, M_, 0);
}